// round 2
// baseline (speedup 1.0000x reference)
#include <cuda_runtime.h>
#include <math.h>

// Problem constants
// x: (4,256,128,128)  xyz: (4,3,128,128)
// folded blocks: NB=128 (b*32 + e*4 + f1*2 + f2), c=32, tile 64x64, M=16 centers
#define NB 128
#define MCNT 16
#define HD 32

// ---------------- scratch (static __device__, no allocation) ----------------
__device__ float  d_cen [NB*MCNT*HD];     // pooled centers (unnormalized)
__device__ float  d_ncen[NB*MCNT*HD];     // l2-normalized centers
__device__ float  d_ngeo[16*MCNT*4];      // normalized xyz centers, padded to 4
__device__ float  d_sim [NB*MCNT*4096];   // 33.5 MB sim cache
__device__ float  d_pre [4*256*128*128];  // 67 MB pre-GroupNorm buffer
__device__ double d_gstats[8];            // per-batch sum, sumsq
__device__ float  d_gn[8];                // per-batch mu, inv_std
__device__ float  d_weff[4*256*256];      // GN-folded projection weights
__device__ float  d_beff[4*256];          // GN-folded projection bias

__device__ __forceinline__ float sigmoidf(float z) { return 1.f / (1.f + __expf(-z)); }

// ---------------- kernel A: pooled centers, warp per (bb,m,c) ----------------
__global__ void k_centers(const float* __restrict__ x) {
    int w = blockIdx.x * 8 + (threadIdx.x >> 5);   // 65536 warps
    int lane = threadIdx.x & 31;
    int bb = w >> 9; int rem = w & 511; int m = rem >> 5; int c = rem & 31;
    int b = bb >> 5, e = (bb >> 2) & 7, f1 = (bb >> 1) & 1, f2 = bb & 1;
    int pi = m >> 2, pj = m & 3;
    const float* xp = x + (((size_t)(b * 256 + e * 32 + c)) << 14)
                        + (f1 * 64 + pi * 16) * 128 + f2 * 64 + pj * 16;
    float acc = 0.f;
    #pragma unroll
    for (int p = lane; p < 256; p += 32) {
        int ii = p >> 4, jj = p & 15;
        acc += xp[ii * 128 + jj];
    }
    #pragma unroll
    for (int o = 16; o; o >>= 1) acc += __shfl_down_sync(0xffffffffu, acc, o);
    if (lane == 0) d_cen[w] = acc * (1.f / 256.f);
}

// ---------------- kernel A2: normalize centers, warp per (bb,m) ----------------
__global__ void k_ncen() {
    int q = blockIdx.x * 8 + (threadIdx.x >> 5);   // 2048 warps
    int c = threadIdx.x & 31;
    float v = d_cen[q * 32 + c];
    float ss = v * v;
    #pragma unroll
    for (int o = 16; o; o >>= 1) ss += __shfl_xor_sync(0xffffffffu, ss, o);
    float inv = 1.f / fmaxf(sqrtf(ss), 1e-12f);
    d_ncen[q * 32 + c] = v * inv;
}

// ---------------- kernel A3: normalized xyz centers + zero stats ----------------
__global__ void k_geo(const float* __restrict__ xyz) {
    int t = threadIdx.x;
    if (t < 8) d_gstats[t] = 0.0;
    int g = t >> 4, m = t & 15;
    int b = g >> 2, f1 = (g >> 1) & 1, f2 = g & 1;
    int pi = m >> 2, pj = m & 3;
    const float* base = xyz + (((size_t)(b * 3)) << 14)
                            + (f1 * 64 + pi * 16) * 128 + f2 * 64 + pj * 16;
    float s0 = 0.f, s1 = 0.f, s2 = 0.f;
    for (int ii = 0; ii < 16; ii++)
        for (int jj = 0; jj < 16; jj++) {
            int off = ii * 128 + jj;
            s0 += base[off];
            s1 += base[off + 16384];
            s2 += base[off + 32768];
        }
    s0 *= (1.f / 256.f); s1 *= (1.f / 256.f); s2 *= (1.f / 256.f);
    float inv = 1.f / fmaxf(sqrtf(s0 * s0 + s1 * s1 + s2 * s2), 1e-12f);
    int o = (g * 16 + m) * 4;
    d_ngeo[o] = s0 * inv; d_ngeo[o + 1] = s1 * inv; d_ngeo[o + 2] = s2 * inv; d_ngeo[o + 3] = 0.f;
}

// ---------------- kernel B: main attention-like pass, CTA per bb ----------------
__global__ __launch_bounds__(256) void k_main(const float* __restrict__ x,
                                              const float* __restrict__ xyz,
                                              const float* __restrict__ salpha,
                                              const float* __restrict__ sbeta) {
    __shared__ float s_cen[512];
    __shared__ float s_ncen[512];
    __shared__ float s_ngeo[16][4];
    __shared__ float s_x[32][65];
    __shared__ float s_inv[64];
    __shared__ float s_g[3][64];
    __shared__ float s_sim[16][68];
    __shared__ float s_S[16];
    __shared__ float s_dout[16][32];
    __shared__ double s_redd[16];

    int bb = blockIdx.x;
    int t = threadIdx.x;
    int b = bb >> 5, e = (bb >> 2) & 7, f1 = (bb >> 1) & 1, f2 = bb & 1;
    int g = bb & 15;        // reference's tile() quirk: geo block = bb % 16
    int bg = g >> 2;        // == e & 3
    float alpha = salpha[0], beta = sbeta[0];

    s_cen[t]        = d_cen[bb * 512 + t];
    s_cen[t + 256]  = d_cen[bb * 512 + t + 256];
    s_ncen[t]       = d_ncen[bb * 512 + t];
    s_ncen[t + 256] = d_ncen[bb * 512 + t + 256];
    if (t < 64) ((float*)s_ngeo)[t] = d_ngeo[g * 64 + t];
    __syncthreads();

    const float* xb = x + (((size_t)(b * 256 + e * 32)) << 14) + (f1 * 64) * 128 + f2 * 64;
    const float* gb = xyz + (((size_t)(bg * 3)) << 14) + (f1 * 64) * 128 + f2 * 64;
    float* simb = d_sim + (size_t)bb * (MCNT * 4096);

    int c4 = t >> 6, j = t & 63;
    int m0 = t >> 5, c0 = t & 31;

    float T0 = 0.f, T1 = 0.f, Sreg = 0.f;

    for (int i = 0; i < 64; i++) {
        // load x row (32 channels x 64 cols) + xyz row
        #pragma unroll
        for (int cc = 0; cc < 8; cc++) {
            int c = cc * 4 + c4;
            s_x[c][j] = xb[c * 16384 + i * 128 + j];
        }
        if (t < 192) {
            int ch = t >> 6, jj = t & 63;
            s_g[ch][jj] = gb[ch * 16384 + i * 128 + jj];
        }
        __syncthreads();
        if (t < 64) {
            float ss = 0.f;
            #pragma unroll
            for (int c = 0; c < 32; c++) { float v = s_x[c][t]; ss += v * v; }
            s_inv[t] = 1.f / fmaxf(sqrtf(ss), 1e-12f);
        } else if (t < 128) {
            int jj = t - 64;
            float g0 = s_g[0][jj], g1 = s_g[1][jj], g2 = s_g[2][jj];
            float inv = 1.f / fmaxf(sqrtf(g0 * g0 + g1 * g1 + g2 * g2), 1e-12f);
            s_g[0][jj] = g0 * inv; s_g[1][jj] = g1 * inv; s_g[2][jj] = g2 * inv;
        }
        __syncthreads();
        // sim tile: thread -> (m, 4 cols)
        {
            int m = t >> 4; int j0 = (t & 15) * 4;
            float d0 = 0.f, d1 = 0.f, d2 = 0.f, d3 = 0.f;
            #pragma unroll
            for (int c = 0; c < 32; c++) {
                float nc = s_ncen[m * 32 + c];
                d0 += nc * s_x[c][j0];
                d1 += nc * s_x[c][j0 + 1];
                d2 += nc * s_x[c][j0 + 2];
                d3 += nc * s_x[c][j0 + 3];
            }
            float ga = s_ngeo[m][0], gbv = s_ngeo[m][1], gc = s_ngeo[m][2];
            float dq[4] = {d0, d1, d2, d3};
            float sv[4];
            #pragma unroll
            for (int q = 0; q < 4; q++) {
                int jj = j0 + q;
                float sfeat = sigmoidf(beta + alpha * dq[q] * s_inv[jj]);
                float gd = ga * s_g[0][jj] + gbv * s_g[1][jj] + gc * s_g[2][jj];
                float sg = sigmoidf(beta + alpha * gd);
                float v = sfeat * sg * sg;
                sv[q] = v;
                s_sim[m][jj] = v;
            }
            *(float4*)(simb + m * 4096 + i * 64 + j0) = make_float4(sv[0], sv[1], sv[2], sv[3]);
        }
        __syncthreads();
        // accumulate T (sim @ xpts, thread owns (m0,c0) and (m0+8,c0)) and S
        #pragma unroll 8
        for (int jj = 0; jj < 64; jj++) {
            float xv = s_x[c0][jj];
            T0 += s_sim[m0][jj] * xv;
            T1 += s_sim[m0 + 8][jj] * xv;
        }
        if (t < 16) {
            float a = 0.f;
            #pragma unroll 8
            for (int jj = 0; jj < 64; jj++) a += s_sim[t][jj];
            Sreg += a;
        }
        __syncthreads();
    }
    if (t < 16) s_S[t] = Sreg;
    __syncthreads();
    s_dout[m0][c0]     = (T0 + s_cen[m0 * 32 + c0]) / (s_S[m0] + 1.f);
    s_dout[m0 + 8][c0] = (T1 + s_cen[(m0 + 8) * 32 + c0]) / (s_S[m0 + 8] + 1.f);
    __syncthreads();

    // phase 3: out[n][c] = sum_m dout[m][c] * sim[m][n], write unfolded + GN stats
    float* pb = d_pre + (((size_t)(b * 256 + e * 32)) << 14) + (f1 * 64) * 128 + f2 * 64;
    float lsum = 0.f, l2 = 0.f;
    for (int i = 0; i < 64; i++) {
        {   // reload sim tile (one float4 per thread)
            int mm = t >> 4, j0 = (t & 15) * 4;
            float4 v = *(const float4*)(simb + mm * 4096 + i * 64 + j0);
            s_sim[mm][j0] = v.x; s_sim[mm][j0 + 1] = v.y;
            s_sim[mm][j0 + 2] = v.z; s_sim[mm][j0 + 3] = v.w;
        }
        __syncthreads();
        #pragma unroll
        for (int cc = 0; cc < 8; cc++) {
            int c = cc * 4 + c4;
            float val = 0.f;
            #pragma unroll
            for (int mm = 0; mm < 16; mm++) val += s_dout[mm][c] * s_sim[mm][j];
            pb[c * 16384 + i * 128 + j] = val;
            lsum += val; l2 += val * val;
        }
        __syncthreads();
    }
    // block-reduce stats into per-batch double accumulators
    double ds = (double)lsum, d2 = (double)l2;
    #pragma unroll
    for (int o = 16; o; o >>= 1) {
        ds += __shfl_down_sync(0xffffffffu, ds, o);
        d2 += __shfl_down_sync(0xffffffffu, d2, o);
    }
    int wid = t >> 5, lane = t & 31;
    if (lane == 0) { s_redd[wid] = ds; s_redd[8 + wid] = d2; }
    __syncthreads();
    if (t == 0) {
        double a = 0.0, bq = 0.0;
        for (int w2 = 0; w2 < 8; w2++) { a += s_redd[w2]; bq += s_redd[8 + w2]; }
        atomicAdd(&d_gstats[b * 2], a);
        atomicAdd(&d_gstats[b * 2 + 1], bq);
    }
}

// ---------------- kernel C: finalize GroupNorm stats ----------------
__global__ void k_gn() {
    int t = threadIdx.x;
    if (t < 4) {
        double cnt = 4194304.0;
        double mu = d_gstats[t * 2] / cnt;
        double var = d_gstats[t * 2 + 1] / cnt - mu * mu;
        d_gn[t * 2] = (float)mu;
        d_gn[t * 2 + 1] = (float)(1.0 / sqrt(var + 1e-5));
    }
}

// ---------------- kernel D: fold GN scale into projection weights ----------------
__global__ void k_weff(const float* __restrict__ Wp, const float* __restrict__ gnw) {
    int idx = blockIdx.x * 256 + threadIdx.x;   // 262144
    int b = idx >> 16, oc = idx & 65535, c = idx & 255;
    d_weff[idx] = Wp[oc] * d_gn[b * 2 + 1] * gnw[c];
}

// ---------------- kernel E: fold GN shift into projection bias ----------------
__global__ void k_beff(const float* __restrict__ Wp, const float* __restrict__ gnw,
                       const float* __restrict__ gnb, const float* __restrict__ bp) {
    int q = blockIdx.x * 8 + (threadIdx.x >> 5);   // 1024 warps
    int lane = threadIdx.x & 31;
    int b = q >> 8, o = q & 255;
    float mu = d_gn[b * 2], inv = d_gn[b * 2 + 1];
    float acc = 0.f;
    for (int c = lane; c < 256; c += 32) {
        float dc = gnb[c] - mu * inv * gnw[c];
        acc += dc * Wp[o * 256 + c];
    }
    #pragma unroll
    for (int off = 16; off; off >>= 1) acc += __shfl_down_sync(0xffffffffu, acc, off);
    if (lane == 0) d_beff[q] = bp[o] + acc;
}

// ---------------- kernel F: fused GN + 1x1 proj GEMM + SiLU ----------------
__global__ __launch_bounds__(256) void k_gemm(float* __restrict__ out) {
    __shared__ float Ws[32][68];
    __shared__ float Ps[32][132];
    int pb = blockIdx.x * 128;
    int ob = blockIdx.y * 64;
    int b = blockIdx.z;
    int t = threadIdx.x;
    int tx = t & 15, ty = t >> 4;
    const float* W = d_weff + b * 65536;
    const float* P = d_pre + (size_t)b * 4194304;

    float acc[4][8];
    #pragma unroll
    for (int a = 0; a < 4; a++)
        #pragma unroll
        for (int q = 0; q < 8; q++) acc[a][q] = 0.f;

    for (int k0 = 0; k0 < 256; k0 += 32) {
        #pragma unroll
        for (int r = 0; r < 2; r++) {
            int f = r * 256 + t;
            int row = f >> 3, col4 = f & 7;
            float4 v = *(const float4*)(W + (ob + row) * 256 + k0 + col4 * 4);
            Ws[col4 * 4 + 0][row] = v.x; Ws[col4 * 4 + 1][row] = v.y;
            Ws[col4 * 4 + 2][row] = v.z; Ws[col4 * 4 + 3][row] = v.w;
        }
        #pragma unroll
        for (int r = 0; r < 4; r++) {
            int f = r * 256 + t;
            int kk = f >> 5, p4 = f & 31;
            float4 v = *(const float4*)(P + (size_t)(k0 + kk) * 16384 + pb + p4 * 4);
            *(float4*)(&Ps[kk][p4 * 4]) = v;
        }
        __syncthreads();
        #pragma unroll
        for (int k = 0; k < 32; k++) {
            float wr[4], pr[8];
            #pragma unroll
            for (int a = 0; a < 4; a++) wr[a] = Ws[k][ty * 4 + a];
            #pragma unroll
            for (int q = 0; q < 8; q++) pr[q] = Ps[k][tx * 8 + q];
            #pragma unroll
            for (int a = 0; a < 4; a++)
                #pragma unroll
                for (int q = 0; q < 8; q++) acc[a][q] += wr[a] * pr[q];
        }
        __syncthreads();
    }
    #pragma unroll
    for (int a = 0; a < 4; a++) {
        int o = ob + ty * 4 + a;
        float bias = d_beff[b * 256 + o];
        float r[8];
        #pragma unroll
        for (int q = 0; q < 8; q++) {
            float z = acc[a][q] + bias;
            r[q] = z * sigmoidf(z);
        }
        float* orow = out + (((size_t)(b * 256 + o)) << 14) + pb + tx * 8;
        *(float4*)orow       = make_float4(r[0], r[1], r[2], r[3]);
        *(float4*)(orow + 4) = make_float4(r[4], r[5], r[6], r[7]);
    }
}

// ---------------- launch ----------------
extern "C" void kernel_launch(void* const* d_in, const int* in_sizes, int n_in,
                              void* d_out, int out_size) {
    const float* x     = (const float*)d_in[0];
    const float* xyz   = (const float*)d_in[1];
    // d_in[2]=Wv, d_in[3]=bv : dead code (split path multiplied by zero mask)
    const float* Wproj = (const float*)d_in[4];
    const float* bproj = (const float*)d_in[5];
    const float* gnw   = (const float*)d_in[6];
    const float* gnb   = (const float*)d_in[7];
    const float* sa    = (const float*)d_in[8];
    const float* sb    = (const float*)d_in[9];
    float* out = (float*)d_out;

    k_centers<<<8192, 256>>>(x);
    k_ncen<<<256, 256>>>();
    k_geo<<<1, 256>>>(xyz);
    k_main<<<128, 256>>>(x, xyz, sa, sb);
    k_gn<<<1, 32>>>();
    k_weff<<<1024, 256>>>(Wproj, gnw);
    k_beff<<<128, 256>>>(Wproj, gnw, gnb, bproj);
    k_gemm<<<dim3(128, 4, 4), 256>>>(out);
}

// round 3
// speedup vs baseline: 1.6682x; 1.6682x over previous
#include <cuda_runtime.h>
#include <math.h>

// x: (4,256,128,128)  xyz: (4,3,128,128)
// folded blocks: NB=128 (b*32 + e*4 + f1*2 + f2), c=32, tile 64x64, M=16 centers
#define NB 128
#define MCNT 16
#define HD 32

// ---------------- scratch (static __device__, no allocation) ----------------
__device__ float  d_cen [NB*MCNT*HD];     // pooled centers (unnormalized)
__device__ float  d_ncen[NB*MCNT*HD];     // l2-normalized centers
__device__ float  d_ngeo[16*MCNT*4];      // normalized xyz centers, padded to 4
__device__ float  d_sim [NB*MCNT*4096];   // 33.5 MB sim cache
__device__ float  d_Tp  [1024*512];       // partial T = sim@x  (per bb-chunk)
__device__ float  d_Sp  [1024*16];        // partial rowsum(sim)
__device__ float  d_Gp  [1024*256];       // partial Gram(sim)
__device__ float  d_dout[NB*512];         // dense_out (16m x 32c per bb)
__device__ double d_gstats[8];            // per-batch sum, sumsq
__device__ float  d_gn[8];                // per-batch mu, inv_std
__device__ float  d_weff[4*256*256];      // GN-folded projection weights
__device__ float  d_beff[4*256];          // GN-folded projection bias
__device__ float  d_WD  [16*256*128];     // fused weights: Weff @ dout^T per tile

__device__ __forceinline__ float sigmoidf(float z) { return 1.f / (1.f + __expf(-z)); }

// ---------------- kernel A: pooled centers, warp per (bb,m,c) ----------------
__global__ void k_centers(const float* __restrict__ x) {
    int w = blockIdx.x * 8 + (threadIdx.x >> 5);   // 65536 warps
    int lane = threadIdx.x & 31;
    int bb = w >> 9; int rem = w & 511; int m = rem >> 5; int c = rem & 31;
    int b = bb >> 5, e = (bb >> 2) & 7, f1 = (bb >> 1) & 1, f2 = bb & 1;
    int pi = m >> 2, pj = m & 3;
    const float* xp = x + (((size_t)(b * 256 + e * 32 + c)) << 14)
                        + (f1 * 64 + pi * 16) * 128 + f2 * 64 + pj * 16;
    float acc = 0.f;
    #pragma unroll
    for (int p = lane; p < 256; p += 32) {
        int ii = p >> 4, jj = p & 15;
        acc += xp[ii * 128 + jj];
    }
    #pragma unroll
    for (int o = 16; o; o >>= 1) acc += __shfl_down_sync(0xffffffffu, acc, o);
    if (lane == 0) d_cen[w] = acc * (1.f / 256.f);
}

// ---------------- kernel A2: normalize centers, warp per (bb,m) ----------------
__global__ void k_ncen() {
    int q = blockIdx.x * 8 + (threadIdx.x >> 5);   // 2048 warps
    int c = threadIdx.x & 31;
    float v = d_cen[q * 32 + c];
    float ss = v * v;
    #pragma unroll
    for (int o = 16; o; o >>= 1) ss += __shfl_xor_sync(0xffffffffu, ss, o);
    float inv = 1.f / fmaxf(sqrtf(ss), 1e-12f);
    d_ncen[q * 32 + c] = v * inv;
}

// ---------------- kernel A3: normalized xyz centers + zero stats ----------------
__global__ void k_geo(const float* __restrict__ xyz) {
    int t = threadIdx.x;
    if (t < 8) d_gstats[t] = 0.0;
    int g = t >> 4, m = t & 15;
    int b = g >> 2, f1 = (g >> 1) & 1, f2 = g & 1;
    int pi = m >> 2, pj = m & 3;
    const float* base = xyz + (((size_t)(b * 3)) << 14)
                            + (f1 * 64 + pi * 16) * 128 + f2 * 64 + pj * 16;
    float s0 = 0.f, s1 = 0.f, s2 = 0.f;
    for (int ii = 0; ii < 16; ii++)
        for (int jj = 0; jj < 16; jj++) {
            int off = ii * 128 + jj;
            s0 += base[off];
            s1 += base[off + 16384];
            s2 += base[off + 32768];
        }
    s0 *= (1.f / 256.f); s1 *= (1.f / 256.f); s2 *= (1.f / 256.f);
    float inv = 1.f / fmaxf(sqrtf(s0 * s0 + s1 * s1 + s2 * s2), 1e-12f);
    int o = (g * 16 + m) * 4;
    d_ngeo[o] = s0 * inv; d_ngeo[o + 1] = s1 * inv; d_ngeo[o + 2] = s2 * inv; d_ngeo[o + 3] = 0.f;
}

// ---------------- kernel B: sim pass, CTA per (bb, 8-row chunk) ----------------
__global__ __launch_bounds__(256) void k_sim(const float* __restrict__ x,
                                             const float* __restrict__ xyz,
                                             const float* __restrict__ salpha,
                                             const float* __restrict__ sbeta) {
    __shared__ float s_ncen[512];
    __shared__ float s_ngeo[16][4];
    __shared__ float s_x[32][65];
    __shared__ float s_inv[64];
    __shared__ float s_g[3][64];
    __shared__ float s_sim[16][67];

    int blk = blockIdx.x;                  // 0..1023
    int bb = blk >> 3, chunk = blk & 7;
    int t = threadIdx.x;
    int b = bb >> 5, e = (bb >> 2) & 7, f1 = (bb >> 1) & 1, f2 = bb & 1;
    int g = bb & 15;        // reference's tile() quirk: geo block = bb % 16
    int bg = g >> 2;
    float alpha = salpha[0], beta = sbeta[0];

    s_ncen[t]       = d_ncen[bb * 512 + t];
    s_ncen[t + 256] = d_ncen[bb * 512 + t + 256];
    if (t < 64) ((float*)s_ngeo)[t] = d_ngeo[g * 64 + t];
    __syncthreads();

    const float* xb = x + (((size_t)(b * 256 + e * 32)) << 14) + (f1 * 64) * 128 + f2 * 64;
    const float* gb = xyz + (((size_t)(bg * 3)) << 14) + (f1 * 64) * 128 + f2 * 64;
    float* simb = d_sim + (size_t)bb * (MCNT * 4096);

    int c4 = t >> 6, j = t & 63;
    int m0 = t >> 5, c0 = t & 31;
    int ma = t >> 4, mb = t & 15;

    float T0 = 0.f, T1 = 0.f, Sreg = 0.f, Greg = 0.f;

    for (int ir = 0; ir < 8; ir++) {
        int i = chunk * 8 + ir;
        #pragma unroll
        for (int cc = 0; cc < 8; cc++) {
            int c = cc * 4 + c4;
            s_x[c][j] = xb[c * 16384 + i * 128 + j];
        }
        if (t < 192) {
            int ch = t >> 6, jj = t & 63;
            s_g[ch][jj] = gb[ch * 16384 + i * 128 + jj];
        }
        __syncthreads();
        if (t < 64) {
            float ss = 0.f;
            #pragma unroll
            for (int c = 0; c < 32; c++) { float v = s_x[c][t]; ss += v * v; }
            s_inv[t] = 1.f / fmaxf(sqrtf(ss), 1e-12f);
        } else if (t < 128) {
            int jj = t - 64;
            float g0 = s_g[0][jj], g1 = s_g[1][jj], g2 = s_g[2][jj];
            float inv = 1.f / fmaxf(sqrtf(g0 * g0 + g1 * g1 + g2 * g2), 1e-12f);
            s_g[0][jj] = g0 * inv; s_g[1][jj] = g1 * inv; s_g[2][jj] = g2 * inv;
        }
        __syncthreads();
        {   // sim tile: thread -> (m, 4 cols)
            int m = t >> 4; int j0 = (t & 15) * 4;
            float d0 = 0.f, d1 = 0.f, d2 = 0.f, d3 = 0.f;
            #pragma unroll
            for (int c = 0; c < 32; c++) {
                float nc = s_ncen[m * 32 + c];
                d0 += nc * s_x[c][j0];
                d1 += nc * s_x[c][j0 + 1];
                d2 += nc * s_x[c][j0 + 2];
                d3 += nc * s_x[c][j0 + 3];
            }
            float ga = s_ngeo[m][0], gbv = s_ngeo[m][1], gc = s_ngeo[m][2];
            float dq[4] = {d0, d1, d2, d3};
            float sv[4];
            #pragma unroll
            for (int q = 0; q < 4; q++) {
                int jj = j0 + q;
                float sfeat = sigmoidf(beta + alpha * dq[q] * s_inv[jj]);
                float gd = ga * s_g[0][jj] + gbv * s_g[1][jj] + gc * s_g[2][jj];
                float sg = sigmoidf(beta + alpha * gd);
                float v = sfeat * sg * sg;
                sv[q] = v;
                s_sim[m][jj] = v;
            }
            *(float4*)(simb + m * 4096 + i * 64 + j0) = make_float4(sv[0], sv[1], sv[2], sv[3]);
        }
        __syncthreads();
        // T (sim @ xpts), S (rowsum), G (Gram)
        #pragma unroll 8
        for (int jj = 0; jj < 64; jj++) {
            float xv = s_x[c0][jj];
            T0 += s_sim[m0][jj] * xv;
            T1 += s_sim[m0 + 8][jj] * xv;
        }
        {
            float ga = 0.f;
            #pragma unroll 8
            for (int jj = 0; jj < 64; jj++) ga += s_sim[ma][jj] * s_sim[mb][jj];
            Greg += ga;
        }
        if (t < 16) {
            float a = 0.f;
            #pragma unroll 8
            for (int jj = 0; jj < 64; jj++) a += s_sim[t][jj];
            Sreg += a;
        }
        __syncthreads();
    }
    d_Tp[blk * 512 + m0 * 32 + c0]       = T0;
    d_Tp[blk * 512 + (m0 + 8) * 32 + c0] = T1;
    d_Gp[blk * 256 + t] = Greg;
    if (t < 16) d_Sp[blk * 16 + t] = Sreg;
}

// ---------- kernel B2: reduce partials -> dout, D, GN stat contributions ----------
__global__ __launch_bounds__(256) void k_dout() {
    __shared__ float s_S[16];
    __shared__ float s_dout[512];
    __shared__ double s_redd[16];
    int bb = blockIdx.x;
    int t = threadIdx.x;
    int b = bb >> 5;

    // reduce S
    if (t < 16) {
        float s = 0.f;
        #pragma unroll
        for (int ch = 0; ch < 8; ch++) s += d_Sp[(bb * 8 + ch) * 16 + t];
        s_S[t] = s;
    }
    // reduce T (2 entries per thread)
    float Ta = 0.f, Tb = 0.f;
    #pragma unroll
    for (int ch = 0; ch < 8; ch++) {
        Ta += d_Tp[(bb * 8 + ch) * 512 + t];
        Tb += d_Tp[(bb * 8 + ch) * 512 + t + 256];
    }
    // reduce G
    float Gf = 0.f;
    #pragma unroll
    for (int ch = 0; ch < 8; ch++) Gf += d_Gp[(bb * 8 + ch) * 256 + t];
    __syncthreads();

    int m1 = t >> 5, m2 = m1 + 8;
    float da = (Ta + d_cen[bb * 512 + t])       / (s_S[m1] + 1.f);
    float db = (Tb + d_cen[bb * 512 + t + 256]) / (s_S[m2] + 1.f);
    s_dout[t] = da; s_dout[t + 256] = db;
    d_dout[bb * 512 + t] = da;
    d_dout[bb * 512 + t + 256] = db;
    __syncthreads();

    // D[ma][mb] = sum_c dout[ma][c]*dout[mb][c]; stats
    int ma = t >> 4, mb = t & 15;
    float D = 0.f;
    #pragma unroll
    for (int c = 0; c < 32; c++) D += s_dout[ma * 32 + c] * s_dout[mb * 32 + c];

    double ds = (double)(da * s_S[m1] + db * s_S[m2]);  // sum(pre) contribution
    double d2 = (double)(Gf * D);                        // sumsq(pre) contribution
    #pragma unroll
    for (int o = 16; o; o >>= 1) {
        ds += __shfl_down_sync(0xffffffffu, ds, o);
        d2 += __shfl_down_sync(0xffffffffu, d2, o);
    }
    int wid = t >> 5, lane = t & 31;
    if (lane == 0) { s_redd[wid] = ds; s_redd[8 + wid] = d2; }
    __syncthreads();
    if (t == 0) {
        double a = 0.0, bq = 0.0;
        for (int w2 = 0; w2 < 8; w2++) { a += s_redd[w2]; bq += s_redd[8 + w2]; }
        atomicAdd(&d_gstats[b * 2], a);
        atomicAdd(&d_gstats[b * 2 + 1], bq);
    }
}

// ---------------- kernel C: finalize GroupNorm stats ----------------
__global__ void k_gn() {
    int t = threadIdx.x;
    if (t < 4) {
        double cnt = 4194304.0;
        double mu = d_gstats[t * 2] / cnt;
        double var = d_gstats[t * 2 + 1] / cnt - mu * mu;
        d_gn[t * 2] = (float)mu;
        d_gn[t * 2 + 1] = (float)(1.0 / sqrt(var + 1e-5));
    }
}

// ---------------- kernel D: fold GN scale into projection weights ----------------
__global__ void k_weff(const float* __restrict__ Wp, const float* __restrict__ gnw) {
    int idx = blockIdx.x * 256 + threadIdx.x;   // 262144
    int b = idx >> 16, oc = idx & 65535, c = idx & 255;
    d_weff[idx] = Wp[oc] * d_gn[b * 2 + 1] * gnw[c];
}

// ---------------- kernel E: fold GN shift into projection bias ----------------
__global__ void k_beff(const float* __restrict__ Wp, const float* __restrict__ gnw,
                       const float* __restrict__ gnb, const float* __restrict__ bp) {
    int q = blockIdx.x * 8 + (threadIdx.x >> 5);   // 1024 warps
    int lane = threadIdx.x & 31;
    int b = q >> 8, o = q & 255;
    float mu = d_gn[b * 2], inv = d_gn[b * 2 + 1];
    float acc = 0.f;
    for (int c = lane; c < 256; c += 32) {
        float dc = gnb[c] - mu * inv * gnw[c];
        acc += dc * Wp[o * 256 + c];
    }
    #pragma unroll
    for (int off = 16; off; off >>= 1) acc += __shfl_down_sync(0xffffffffu, acc, off);
    if (lane == 0) d_beff[q] = bp[o] + acc;
}

// -------- kernel WD: WD[tile][o][e*16+m] = sum_c Weff[b][o][e*32+c]*dout[bb][m][c] --------
__global__ __launch_bounds__(256) void k_wd() {
    __shared__ float s_dout[512];
    int bb = blockIdx.x;
    int t = threadIdx.x;
    int b = bb >> 5, e = (bb >> 2) & 7;
    int tile = b * 4 + (bb & 3);            // (b, f1, f2)
    s_dout[t] = d_dout[bb * 512 + t];
    s_dout[t + 256] = d_dout[bb * 512 + t + 256];
    __syncthreads();
    const float* W = d_weff + b * 65536 + t * 256 + e * 32;   // row o=t
    float acc[16];
    #pragma unroll
    for (int m = 0; m < 16; m++) acc[m] = 0.f;
    #pragma unroll
    for (int c = 0; c < 32; c++) {
        float wv = W[c];
        #pragma unroll
        for (int m = 0; m < 16; m++) acc[m] += wv * s_dout[m * 32 + c];
    }
    float* dst = d_WD + tile * 32768 + t * 128 + e * 16;
    #pragma unroll
    for (int m = 0; m < 16; m++) dst[m] = acc[m];
}

// -------- kernel F: out[o][n] = silu(beff[o] + sum_q WD[o][q]*sim[q][n]) --------
__global__ __launch_bounds__(256) void k_out(float* __restrict__ out) {
    __shared__ float Ws[32][68];
    __shared__ float Ps[32][132];
    int nb = blockIdx.x * 128;
    int ob = blockIdx.y * 64;
    int tile = blockIdx.z;
    int b = tile >> 2, f1 = (tile >> 1) & 1, f2 = tile & 1;
    int t = threadIdx.x;
    int tx = t & 15, ty = t >> 4;
    const float* W = d_WD + tile * 32768;

    float acc[4][8];
    #pragma unroll
    for (int a = 0; a < 4; a++)
        #pragma unroll
        for (int q = 0; q < 8; q++) acc[a][q] = 0.f;

    for (int k0 = 0; k0 < 128; k0 += 32) {
        #pragma unroll
        for (int r = 0; r < 2; r++) {
            int f = r * 256 + t;
            int row = f >> 3, col4 = f & 7;
            float4 v = *(const float4*)(W + (ob + row) * 128 + k0 + col4 * 4);
            Ws[col4 * 4 + 0][row] = v.x; Ws[col4 * 4 + 1][row] = v.y;
            Ws[col4 * 4 + 2][row] = v.z; Ws[col4 * 4 + 3][row] = v.w;
        }
        #pragma unroll
        for (int r = 0; r < 4; r++) {
            int f = r * 256 + t;
            int kk = f >> 5, p4 = f & 31;
            int q = k0 + kk;                // q = e*16 + m
            int bbq = b * 32 + (q >> 4) * 4 + f1 * 2 + f2;
            const float* srow = d_sim + (size_t)bbq * 65536 + (q & 15) * 4096 + nb;
            float4 v = *(const float4*)(srow + p4 * 4);
            *(float4*)(&Ps[kk][p4 * 4]) = v;
        }
        __syncthreads();
        #pragma unroll
        for (int k = 0; k < 32; k++) {
            float wr[4], pr[8];
            #pragma unroll
            for (int a = 0; a < 4; a++) wr[a] = Ws[k][ty * 4 + a];
            #pragma unroll
            for (int q = 0; q < 8; q++) pr[q] = Ps[k][tx * 8 + q];
            #pragma unroll
            for (int a = 0; a < 4; a++)
                #pragma unroll
                for (int q = 0; q < 8; q++) acc[a][q] += wr[a] * pr[q];
        }
        __syncthreads();
    }
    int nloc = nb + tx * 8;                 // local n within 64x64 tile
    int irow = nloc >> 6, jcol = nloc & 63;
    #pragma unroll
    for (int a = 0; a < 4; a++) {
        int o = ob + ty * 4 + a;
        float bias = d_beff[b * 256 + o];
        float r[8];
        #pragma unroll
        for (int q = 0; q < 8; q++) {
            float z = acc[a][q] + bias;
            r[q] = z * sigmoidf(z);
        }
        float* orow = out + (((size_t)(b * 256 + o)) << 14)
                          + (f1 * 64 + irow) * 128 + f2 * 64 + jcol;
        *(float4*)orow       = make_float4(r[0], r[1], r[2], r[3]);
        *(float4*)(orow + 4) = make_float4(r[4], r[5], r[6], r[7]);
    }
}

// ---------------- launch ----------------
extern "C" void kernel_launch(void* const* d_in, const int* in_sizes, int n_in,
                              void* d_out, int out_size) {
    const float* x     = (const float*)d_in[0];
    const float* xyz   = (const float*)d_in[1];
    // d_in[2]=Wv, d_in[3]=bv : dead code (split path multiplied by zero mask)
    const float* Wproj = (const float*)d_in[4];
    const float* bproj = (const float*)d_in[5];
    const float* gnw   = (const float*)d_in[6];
    const float* gnb   = (const float*)d_in[7];
    const float* sa    = (const float*)d_in[8];
    const float* sb    = (const float*)d_in[9];
    float* out = (float*)d_out;

    k_centers<<<8192, 256>>>(x);
    k_ncen<<<256, 256>>>();
    k_geo<<<1, 256>>>(xyz);
    k_sim<<<1024, 256>>>(x, xyz, sa, sb);
    k_dout<<<128, 256>>>();
    k_gn<<<1, 32>>>();
    k_weff<<<1024, 256>>>(Wproj, gnw);
    k_beff<<<128, 256>>>(Wproj, gnw, gnb, bproj);
    k_wd<<<128, 256>>>();
    k_out<<<dim3(32, 4, 16), 256>>>(out);
}

// round 6
// speedup vs baseline: 1.8270x; 1.0952x over previous
#include <cuda_runtime.h>
#include <math.h>

// x: (4,256,128,128)  xyz: (4,3,128,128)
// folded blocks: NB=128 (b*32 + e*4 + f1*2 + f2), c=32, tile 64x64, M=16 centers
#define NB 128
#define MCNT 16

// ---------------- scratch (static __device__, no allocation) ----------------
__device__ float  d_cen [NB*512];         // pooled centers (unnormalized)
__device__ float  d_ncen[NB*512];         // l2-normalized centers
__device__ float  d_ngeo[16*16*4];        // normalized xyz centers, padded to 4
__device__ float  d_sim [NB*16*4096];     // 33.5 MB sim cache
__device__ float  d_Tp  [1024*512];       // partial T = sim@x  (per bb-chunk)
__device__ float  d_Sp  [1024*16];        // partial rowsum(sim)
__device__ float  d_Gp  [1024*256];       // partial Gram(sim)
__device__ float  d_dout[NB*512];         // dense_out (16m x 32c per bb)
__device__ double d_gstats[8];            // per-batch sum, sumsq
__device__ float  d_weff[4*256*256];      // GN-folded projection weights
__device__ float  d_beff[4*256];          // GN-folded projection bias
__device__ float  d_WD  [16*256*128];     // fused weights: Weff @ dout^T per tile

__device__ __forceinline__ float sigmoidf(float z) { return 1.f / (1.f + __expf(-z)); }

// ---------------- kernel A: pooled centers, warp per (bb,m,c), float4 ----------------
__global__ void k_centers(const float* __restrict__ x) {
    int w = blockIdx.x * 8 + (threadIdx.x >> 5);   // 65536 warps
    int lane = threadIdx.x & 31;
    int bb = w >> 9; int rem = w & 511; int m = rem >> 5; int c = rem & 31;
    int b = bb >> 5, e = (bb >> 2) & 7, f1 = (bb >> 1) & 1, f2 = bb & 1;
    int pi = m >> 2, pj = m & 3;
    const float* xp = x + (((size_t)(b * 256 + e * 32 + c)) << 14)
                        + (f1 * 64 + pi * 16) * 128 + f2 * 64 + pj * 16;
    float acc = 0.f;
    #pragma unroll
    for (int r = 0; r < 2; r++) {
        int idx = r * 32 + lane;              // 0..63 float4s
        int ii = idx >> 2, jj4 = idx & 3;
        float4 v = *(const float4*)(xp + ii * 128 + jj4 * 4);
        acc += (v.x + v.y) + (v.z + v.w);
    }
    #pragma unroll
    for (int o = 16; o; o >>= 1) acc += __shfl_down_sync(0xffffffffu, acc, o);
    if (lane == 0) d_cen[w] = acc * (1.f / 256.f);
}

// ---------------- kernel A2: normalize centers, warp per (bb,m) ----------------
__global__ void k_ncen() {
    int q = blockIdx.x * 8 + (threadIdx.x >> 5);   // 2048 warps
    int c = threadIdx.x & 31;
    float v = d_cen[q * 32 + c];
    float ss = v * v;
    #pragma unroll
    for (int o = 16; o; o >>= 1) ss += __shfl_xor_sync(0xffffffffu, ss, o);
    float inv = 1.f / fmaxf(sqrtf(ss), 1e-12f);
    d_ncen[q * 32 + c] = v * inv;
}

// ---------------- kernel A3: normalized xyz centers + zero stats ----------------
__global__ void k_geo(const float* __restrict__ xyz) {
    int t = threadIdx.x;
    if (t < 8) d_gstats[t] = 0.0;
    int g = t >> 4, m = t & 15;
    int b = g >> 2, f1 = (g >> 1) & 1, f2 = g & 1;
    int pi = m >> 2, pj = m & 3;
    const float* base = xyz + (((size_t)(b * 3)) << 14)
                            + (f1 * 64 + pi * 16) * 128 + f2 * 64 + pj * 16;
    float s0 = 0.f, s1 = 0.f, s2 = 0.f;
    for (int ii = 0; ii < 16; ii++)
        for (int jj = 0; jj < 16; jj++) {
            int off = ii * 128 + jj;
            s0 += base[off];
            s1 += base[off + 16384];
            s2 += base[off + 32768];
        }
    s0 *= (1.f / 256.f); s1 *= (1.f / 256.f); s2 *= (1.f / 256.f);
    float inv = 1.f / fmaxf(sqrtf(s0 * s0 + s1 * s1 + s2 * s2), 1e-12f);
    int o = (g * 16 + m) * 4;
    d_ngeo[o] = s0 * inv; d_ngeo[o + 1] = s1 * inv; d_ngeo[o + 2] = s2 * inv; d_ngeo[o + 3] = 0.f;
}

// ---------------- kernel B: sim pass, CTA per (bb, 8-row chunk) ----------------
// thread = (m = t>>4, jq = t&15): owns sim[m][j0..j0+3] in registers.
__global__ __launch_bounds__(256) void k_sim(const float* __restrict__ x,
                                             const float* __restrict__ xyz,
                                             const float* __restrict__ salpha,
                                             const float* __restrict__ sbeta) {
    __shared__ float s_ncen[512];
    __shared__ float s_ngeo[16][4];
    __shared__ float s_x[32][68];
    __shared__ float s_inv[64];
    __shared__ float s_g[3][64];
    __shared__ float s_sim[16][68];

    int blk = blockIdx.x;                  // 0..1023
    int bb = blk >> 3, chunk = blk & 7;
    int t = threadIdx.x;
    int m = t >> 4, jq = t & 15, j0 = jq * 4;
    int b = bb >> 5, e = (bb >> 2) & 7, f1 = (bb >> 1) & 1, f2 = bb & 1;
    int g = bb & 15;        // reference's tile() quirk: geo block = bb % 16
    int bg = g >> 2;
    float alpha = salpha[0], beta = sbeta[0];

    s_ncen[t]       = d_ncen[bb * 512 + t];
    s_ncen[t + 256] = d_ncen[bb * 512 + t + 256];
    if (t < 64) ((float*)s_ngeo)[t] = d_ngeo[g * 64 + t];

    const float* xb = x + (((size_t)(b * 256 + e * 32)) << 14) + (f1 * 64) * 128 + f2 * 64;
    const float* gb = xyz + (((size_t)(bg * 3)) << 14) + (f1 * 64) * 128 + f2 * 64;
    float* simb = d_sim + (size_t)bb * 65536;

    float Tacc[32];
    #pragma unroll
    for (int c = 0; c < 32; c++) Tacc[c] = 0.f;
    float Sreg = 0.f, Greg = 0.f;
    __syncthreads();

    for (int ir = 0; ir < 8; ir++) {
        int i = chunk * 8 + ir;
        // load x tile 32x64 (512 float4, 2 per thread) + xyz rows (48 float4)
        #pragma unroll
        for (int r = 0; r < 2; r++) {
            int v = r * 256 + t;
            int c = v >> 4, j4 = v & 15;
            *(float4*)&s_x[c][j4 * 4] = *(const float4*)(xb + c * 16384 + i * 128 + j4 * 4);
        }
        if (t < 48) {
            int ch = t >> 4, j4 = t & 15;
            *(float4*)&s_g[ch][j4 * 4] = *(const float4*)(gb + ch * 16384 + i * 128 + j4 * 4);
        }
        __syncthreads();
        if (t < 64) {
            float ss = 0.f;
            #pragma unroll
            for (int c = 0; c < 32; c++) { float v = s_x[c][t]; ss += v * v; }
            s_inv[t] = 1.f / fmaxf(sqrtf(ss), 1e-12f);
        } else if (t < 128) {
            int jj = t - 64;
            float g0 = s_g[0][jj], g1 = s_g[1][jj], g2 = s_g[2][jj];
            float inv = 1.f / fmaxf(sqrtf(g0 * g0 + g1 * g1 + g2 * g2), 1e-12f);
            s_g[0][jj] = g0 * inv; s_g[1][jj] = g1 * inv; s_g[2][jj] = g2 * inv;
        }
        __syncthreads();
        // dot products (float4 LDS on x)
        float d0 = 0.f, d1 = 0.f, d2 = 0.f, d3 = 0.f;
        #pragma unroll
        for (int c = 0; c < 32; c++) {
            float nc = s_ncen[m * 32 + c];
            float4 xq = *(const float4*)&s_x[c][j0];
            d0 += nc * xq.x; d1 += nc * xq.y; d2 += nc * xq.z; d3 += nc * xq.w;
        }
        float ga = s_ngeo[m][0], gbv = s_ngeo[m][1], gc = s_ngeo[m][2];
        float dq[4] = {d0, d1, d2, d3};
        float sv[4];
        #pragma unroll
        for (int q = 0; q < 4; q++) {
            int jj = j0 + q;
            float sfeat = sigmoidf(beta + alpha * dq[q] * s_inv[jj]);
            float gd = ga * s_g[0][jj] + gbv * s_g[1][jj] + gc * s_g[2][jj];
            float sg = sigmoidf(beta + alpha * gd);
            sv[q] = sfeat * sg * sg;
            Sreg += sv[q];
        }
        *(float4*)&s_sim[m][j0] = make_float4(sv[0], sv[1], sv[2], sv[3]);
        *(float4*)(simb + m * 4096 + i * 64 + j0) = make_float4(sv[0], sv[1], sv[2], sv[3]);
        __syncthreads();
        // T from registers: Tacc[c] += dot(sv, x[c][j0:4])
        #pragma unroll
        for (int c = 0; c < 32; c++) {
            float4 xq = *(const float4*)&s_x[c][j0];
            Tacc[c] += sv[0] * xq.x + sv[1] * xq.y + sv[2] * xq.z + sv[3] * xq.w;
        }
        // Gram: thread = (ma=m, mb=jq), float4 over k
        #pragma unroll
        for (int k4 = 0; k4 < 16; k4++) {
            float4 a = *(const float4*)&s_sim[m][k4 * 4];
            float4 bq = *(const float4*)&s_sim[jq][k4 * 4];
            Greg += a.x * bq.x + a.y * bq.y + a.z * bq.z + a.w * bq.w;
        }
        __syncthreads();
    }
    // reductions: S and T over the 16 jq threads of each m (width-16 shuffles)
    #pragma unroll
    for (int o = 8; o; o >>= 1) Sreg += __shfl_down_sync(0xffffffffu, Sreg, o, 16);
    if (jq == 0) d_Sp[blk * 16 + m] = Sreg;
    d_Gp[blk * 256 + t] = Greg;
    #pragma unroll
    for (int c = 0; c < 32; c++) {
        float v = Tacc[c];
        #pragma unroll
        for (int o = 8; o; o >>= 1) v += __shfl_down_sync(0xffffffffu, v, o, 16);
        if (jq == 0) d_Tp[blk * 512 + m * 32 + c] = v;
    }
}

// ---------- kernel B2: reduce partials -> dout, D, GN stat contributions ----------
__global__ __launch_bounds__(256) void k_dout() {
    __shared__ float s_S[16];
    __shared__ float s_dout[512];
    __shared__ double s_redd[16];
    int bb = blockIdx.x;
    int t = threadIdx.x;
    int b = bb >> 5;

    if (t < 16) {
        float s = 0.f;
        #pragma unroll
        for (int ch = 0; ch < 8; ch++) s += d_Sp[(bb * 8 + ch) * 16 + t];
        s_S[t] = s;
    }
    float Ta = 0.f, Tb = 0.f;
    #pragma unroll
    for (int ch = 0; ch < 8; ch++) {
        Ta += d_Tp[(bb * 8 + ch) * 512 + t];
        Tb += d_Tp[(bb * 8 + ch) * 512 + t + 256];
    }
    float Gf = 0.f;
    #pragma unroll
    for (int ch = 0; ch < 8; ch++) Gf += d_Gp[(bb * 8 + ch) * 256 + t];
    __syncthreads();

    int m1 = t >> 5, m2 = m1 + 8;
    float da = (Ta + d_cen[bb * 512 + t])       / (s_S[m1] + 1.f);
    float db = (Tb + d_cen[bb * 512 + t + 256]) / (s_S[m2] + 1.f);
    s_dout[t] = da; s_dout[t + 256] = db;
    d_dout[bb * 512 + t] = da;
    d_dout[bb * 512 + t + 256] = db;
    __syncthreads();

    int ma = t >> 4, mb = t & 15;
    float D = 0.f;
    #pragma unroll
    for (int c = 0; c < 32; c++) D += s_dout[ma * 32 + c] * s_dout[mb * 32 + c];

    double ds = (double)(da * s_S[m1] + db * s_S[m2]);  // sum(pre) contribution
    double d2 = (double)(Gf * D);                        // sumsq(pre) contribution
    #pragma unroll
    for (int o = 16; o; o >>= 1) {
        ds += __shfl_down_sync(0xffffffffu, ds, o);
        d2 += __shfl_down_sync(0xffffffffu, d2, o);
    }
    int wid = t >> 5, lane = t & 31;
    if (lane == 0) { s_redd[wid] = ds; s_redd[8 + wid] = d2; }
    __syncthreads();
    if (t == 0) {
        double a = 0.0, bq = 0.0;
        for (int w2 = 0; w2 < 8; w2++) { a += s_redd[w2]; bq += s_redd[8 + w2]; }
        atomicAdd(&d_gstats[b * 2], a);
        atomicAdd(&d_gstats[b * 2 + 1], bq);
    }
}

// ---------------- kernel D: fold GN scale into projection weights ----------------
__global__ void k_weff(const float* __restrict__ Wp, const float* __restrict__ gnw) {
    int idx = blockIdx.x * 256 + threadIdx.x;   // 262144
    int b = idx >> 16, oc = idx & 65535, c = idx & 255;
    double cnt = 4194304.0;
    double mu = d_gstats[b * 2] / cnt;
    double var = d_gstats[b * 2 + 1] / cnt - mu * mu;
    float inv = (float)(1.0 / sqrt(var + 1e-5));
    d_weff[idx] = Wp[oc] * inv * gnw[c];
}

// ---------------- kernel E: fold GN shift into projection bias ----------------
__global__ void k_beff(const float* __restrict__ Wp, const float* __restrict__ gnw,
                       const float* __restrict__ gnb, const float* __restrict__ bp) {
    int q = blockIdx.x * 8 + (threadIdx.x >> 5);   // 1024 warps
    int lane = threadIdx.x & 31;
    int b = q >> 8, o = q & 255;
    double cnt = 4194304.0;
    double mud = d_gstats[b * 2] / cnt;
    double var = d_gstats[b * 2 + 1] / cnt - mud * mud;
    float inv = (float)(1.0 / sqrt(var + 1e-5));
    float mu = (float)mud;
    float acc = 0.f;
    for (int c = lane; c < 256; c += 32) {
        float dc = gnb[c] - mu * inv * gnw[c];
        acc += dc * Wp[o * 256 + c];
    }
    #pragma unroll
    for (int off = 16; off; off >>= 1) acc += __shfl_down_sync(0xffffffffu, acc, off);
    if (lane == 0) d_beff[q] = bp[o] + acc;
}

// -------- kernel WD: WD[tile][o][e*16+m] = sum_c Weff[b][o][e*32+c]*dout[bb][m][c] --------
__global__ __launch_bounds__(256) void k_wd() {
    __shared__ float s_dout[512];
    int bb = blockIdx.x;
    int t = threadIdx.x;
    int b = bb >> 5, e = (bb >> 2) & 7;
    int tile = b * 4 + (bb & 3);            // (b, f1, f2)
    s_dout[t] = d_dout[bb * 512 + t];
    s_dout[t + 256] = d_dout[bb * 512 + t + 256];
    __syncthreads();
    const float* W = d_weff + b * 65536 + t * 256 + e * 32;   // row o=t
    float acc[16];
    #pragma unroll
    for (int m = 0; m < 16; m++) acc[m] = 0.f;
    #pragma unroll
    for (int c = 0; c < 32; c++) {
        float wv = W[c];
        #pragma unroll
        for (int m = 0; m < 16; m++) acc[m] += wv * s_dout[m * 32 + c];
    }
    float* dst = d_WD + tile * 32768 + t * 128 + e * 16;
    #pragma unroll
    for (int m = 0; m < 16; m++) dst[m] = acc[m];
}

// -------- kernel F: out[o][n] = silu(beff[o] + sum_q WD[o][q]*sim[q][n]) --------
// 128o x 128n per CTA, 8x8 register tile per thread, K=128 in chunks of 16.
__global__ __launch_bounds__(256) void k_out(float* __restrict__ out) {
    __shared__ float Ws[16][132];
    __shared__ float Ps[16][132];
    int nb = blockIdx.x * 128;              // 32 blocks
    int ob = blockIdx.y * 128;              // 2 blocks
    int tile = blockIdx.z;                  // 16
    int b = tile >> 2, f1 = (tile >> 1) & 1, f2 = tile & 1;
    int t = threadIdx.x;
    int tx = t & 15, ty = t >> 4;
    const float* W = d_WD + tile * 32768;

    float acc[8][8];
    #pragma unroll
    for (int a = 0; a < 8; a++)
        #pragma unroll
        for (int q = 0; q < 8; q++) acc[a][q] = 0.f;

    for (int k0 = 0; k0 < 128; k0 += 16) {
        #pragma unroll
        for (int r = 0; r < 2; r++) {       // W: 128o x 16k, transpose to Ws[k][o]
            int v = r * 256 + t;
            int o = v >> 2, k4 = v & 3;
            float4 w4 = *(const float4*)(W + (ob + o) * 128 + k0 + k4 * 4);
            Ws[k4 * 4 + 0][o] = w4.x; Ws[k4 * 4 + 1][o] = w4.y;
            Ws[k4 * 4 + 2][o] = w4.z; Ws[k4 * 4 + 3][o] = w4.w;
        }
        #pragma unroll
        for (int r = 0; r < 2; r++) {       // P: 16k x 128n, direct copy
            int v = r * 256 + t;
            int k = v >> 5, n4 = v & 31;
            int q = k0 + k;                 // q = e*16 + m
            int bbq = b * 32 + (q >> 4) * 4 + f1 * 2 + f2;
            const float* srow = d_sim + (size_t)bbq * 65536 + (q & 15) * 4096 + nb;
            *(float4*)&Ps[k][n4 * 4] = *(const float4*)(srow + n4 * 4);
        }
        __syncthreads();
        #pragma unroll
        for (int k = 0; k < 16; k++) {
            float wr[8], pr[8];
            *(float4*)wr       = *(const float4*)&Ws[k][ty * 8];
            *(float4*)(wr + 4) = *(const float4*)&Ws[k][ty * 8 + 4];
            *(float4*)pr       = *(const float4*)&Ps[k][tx * 8];
            *(float4*)(pr + 4) = *(const float4*)&Ps[k][tx * 8 + 4];
            #pragma unroll
            for (int a = 0; a < 8; a++)
                #pragma unroll
                for (int q = 0; q < 8; q++) acc[a][q] += wr[a] * pr[q];
        }
        __syncthreads();
    }
    int nloc = nb + tx * 8;                 // local n within 64x64 tile
    int irow = nloc >> 6, jcol = nloc & 63;
    #pragma unroll
    for (int a = 0; a < 8; a++) {
        int o = ob + ty * 8 + a;
        float bias = d_beff[b * 256 + o];
        float r[8];
        #pragma unroll
        for (int q = 0; q < 8; q++) {
            float z = acc[a][q] + bias;
            r[q] = z * sigmoidf(z);
        }
        float* orow = out + (((size_t)(b * 256 + o)) << 14)
                          + (f1 * 64 + irow) * 128 + f2 * 64 + jcol;
        *(float4*)orow       = make_float4(r[0], r[1], r[2], r[3]);
        *(float4*)(orow + 4) = make_float4(r[4], r[5], r[6], r[7]);
    }
}

// ---------------- launch ----------------
extern "C" void kernel_launch(void* const* d_in, const int* in_sizes, int n_in,
                              void* d_out, int out_size) {
    const float* x     = (const float*)d_in[0];
    const float* xyz   = (const float*)d_in[1];
    // d_in[2]=Wv, d_in[3]=bv : dead code (split path multiplied by zero mask)
    const float* Wproj = (const float*)d_in[4];
    const float* bproj = (const float*)d_in[5];
    const float* gnw   = (const float*)d_in[6];
    const float* gnb   = (const float*)d_in[7];
    const float* sa    = (const float*)d_in[8];
    const float* sb    = (const float*)d_in[9];
    float* out = (float*)d_out;

    k_centers<<<8192, 256>>>(x);
    k_ncen<<<256, 256>>>();
    k_geo<<<1, 256>>>(xyz);
    k_sim<<<1024, 256>>>(x, xyz, sa, sb);
    k_dout<<<128, 256>>>();
    k_weff<<<1024, 256>>>(Wproj, gnw);
    k_beff<<<128, 256>>>(Wproj, gnw, gnb, bproj);
    k_wd<<<128, 256>>>();
    k_out<<<dim3(32, 2, 16), 256>>>(out);
}

// round 7
// speedup vs baseline: 1.9718x; 1.0792x over previous
#include <cuda_runtime.h>
#include <math.h>

// x: (4,256,128,128)  xyz: (4,3,128,128)
// folded blocks: NB=128 (b*32 + e*4 + f1*2 + f2), c=32, tile 64x64, M=16 centers
#define NB 128
#define MCNT 16

// ---------------- scratch (static __device__, no allocation) ----------------
__device__ float  d_cen [NB*512];         // pooled centers (unnormalized)
__device__ float  d_ncen[NB*512];         // l2-normalized centers
__device__ float  d_ngeo[16*16*4];        // normalized xyz centers, padded to 4
__device__ float  d_sgeo2[16*16*4096];    // sigmoid(geo)^2 table  [g][m][n]  (4 MB)
__device__ float  d_sim [NB*16*4096];     // 33.5 MB sim cache
__device__ float  d_Tp  [1024*512];       // partial T = sim@x  (per bb-chunk)
__device__ float  d_Sp  [1024*16];        // partial rowsum(sim)
__device__ float  d_Gp  [1024*256];       // partial Gram(sim)
__device__ float  d_dout[NB*512];         // dense_out (16m x 32c per bb)
__device__ double d_gstats[8];            // per-batch sum, sumsq
__device__ float  d_weff[4*256*256];      // GN-folded projection weights
__device__ float  d_beff[4*256];          // GN-folded projection bias
__device__ float  d_WD  [16*256*128];     // fused weights: Weff @ dout^T per tile

__device__ __forceinline__ float sigmoidf(float z) { return 1.f / (1.f + __expf(-z)); }

// ---------------- kernel A: pooled centers, warp per (bb,m,c), float4 ----------------
__global__ void k_centers(const float* __restrict__ x) {
    int w = blockIdx.x * 8 + (threadIdx.x >> 5);   // 65536 warps
    int lane = threadIdx.x & 31;
    int bb = w >> 9; int rem = w & 511; int m = rem >> 5; int c = rem & 31;
    int b = bb >> 5, e = (bb >> 2) & 7, f1 = (bb >> 1) & 1, f2 = bb & 1;
    int pi = m >> 2, pj = m & 3;
    const float* xp = x + (((size_t)(b * 256 + e * 32 + c)) << 14)
                        + (f1 * 64 + pi * 16) * 128 + f2 * 64 + pj * 16;
    float acc = 0.f;
    #pragma unroll
    for (int r = 0; r < 2; r++) {
        int idx = r * 32 + lane;              // 0..63 float4s
        int ii = idx >> 2, jj4 = idx & 3;
        float4 v = *(const float4*)(xp + ii * 128 + jj4 * 4);
        acc += (v.x + v.y) + (v.z + v.w);
    }
    #pragma unroll
    for (int o = 16; o; o >>= 1) acc += __shfl_down_sync(0xffffffffu, acc, o);
    if (lane == 0) d_cen[w] = acc * (1.f / 256.f);
}

// ---------------- kernel A2: normalize centers, warp per (bb,m) ----------------
__global__ void k_ncen() {
    int q = blockIdx.x * 8 + (threadIdx.x >> 5);   // 2048 warps
    int c = threadIdx.x & 31;
    float v = d_cen[q * 32 + c];
    float ss = v * v;
    #pragma unroll
    for (int o = 16; o; o >>= 1) ss += __shfl_xor_sync(0xffffffffu, ss, o);
    float inv = 1.f / fmaxf(sqrtf(ss), 1e-12f);
    d_ncen[q * 32 + c] = v * inv;
}

// ---------------- kernel A3: normalized xyz centers + zero stats ----------------
__global__ void k_geo(const float* __restrict__ xyz) {
    int t = threadIdx.x;
    if (t < 8) d_gstats[t] = 0.0;
    int g = t >> 4, m = t & 15;
    int b = g >> 2, f1 = (g >> 1) & 1, f2 = g & 1;
    int pi = m >> 2, pj = m & 3;
    const float* base = xyz + (((size_t)(b * 3)) << 14)
                            + (f1 * 64 + pi * 16) * 128 + f2 * 64 + pj * 16;
    float s0 = 0.f, s1 = 0.f, s2 = 0.f;
    for (int ii = 0; ii < 16; ii++)
        for (int jj = 0; jj < 16; jj++) {
            int off = ii * 128 + jj;
            s0 += base[off];
            s1 += base[off + 16384];
            s2 += base[off + 32768];
        }
    s0 *= (1.f / 256.f); s1 *= (1.f / 256.f); s2 *= (1.f / 256.f);
    float inv = 1.f / fmaxf(sqrtf(s0 * s0 + s1 * s1 + s2 * s2), 1e-12f);
    int o = (g * 16 + m) * 4;
    d_ngeo[o] = s0 * inv; d_ngeo[o + 1] = s1 * inv; d_ngeo[o + 2] = s2 * inv; d_ngeo[o + 3] = 0.f;
}

// ---------------- kernel A4: sim_geo^2 table [g][m][n], grid (16 g, 64 i) ----------------
__global__ void k_geo2(const float* __restrict__ xyz,
                       const float* __restrict__ salpha, const float* __restrict__ sbeta) {
    int g = blockIdx.x, i = blockIdx.y;
    int t = threadIdx.x;
    int j = t & 63, mg = t >> 6;                 // 4 m-groups of 4
    int bg = g >> 2, f1 = (g >> 1) & 1, f2 = g & 1;
    float alpha = salpha[0], beta = sbeta[0];
    const float* base = xyz + (((size_t)(bg * 3)) << 14) + (f1 * 64 + i) * 128 + f2 * 64 + j;
    float p0 = base[0], p1 = base[16384], p2 = base[32768];
    float inv = 1.f / fmaxf(sqrtf(p0 * p0 + p1 * p1 + p2 * p2), 1e-12f);
    p0 *= inv; p1 *= inv; p2 *= inv;
    #pragma unroll
    for (int mm = 0; mm < 4; mm++) {
        int m = mg * 4 + mm;
        const float* ng = d_ngeo + (g * 16 + m) * 4;
        float gd = ng[0] * p0 + ng[1] * p1 + ng[2] * p2;
        float sg = sigmoidf(beta + alpha * gd);
        d_sgeo2[(g * 16 + m) * 4096 + i * 64 + j] = sg * sg;
    }
}

// ---------------- kernel B: sim pass (lean), CTA per (bb, 8-row chunk) ----------------
// thread = (m = t>>4, jq = t&15): computes sim[m][j0..j0+3] and stores; no reductions here.
__global__ __launch_bounds__(256) void k_sim(const float* __restrict__ x,
                                             const float* __restrict__ salpha,
                                             const float* __restrict__ sbeta) {
    __shared__ float s_ncen[512];
    __shared__ float s_x[32][68];

    int blk = blockIdx.x;                  // 0..1023
    int bb = blk >> 3, chunk = blk & 7;
    int t = threadIdx.x;
    int m = t >> 4, jq = t & 15, j0 = jq * 4;
    int b = bb >> 5, e = (bb >> 2) & 7, f1 = (bb >> 1) & 1, f2 = bb & 1;
    int g = bb & 15;        // reference's tile() quirk: geo block = bb % 16
    float alpha = salpha[0], beta = sbeta[0];

    s_ncen[t]       = d_ncen[bb * 512 + t];
    s_ncen[t + 256] = d_ncen[bb * 512 + t + 256];

    const float* xb = x + (((size_t)(b * 256 + e * 32)) << 14) + (f1 * 64) * 128 + f2 * 64;
    float* simb = d_sim + (size_t)bb * 65536 + m * 4096;
    const float* sgb = d_sgeo2 + (g * 16 + m) * 4096;
    __syncthreads();

    for (int ir = 0; ir < 8; ir++) {
        int i = chunk * 8 + ir;
        #pragma unroll
        for (int r = 0; r < 2; r++) {
            int v = r * 256 + t;
            int c = v >> 4, j4 = v & 15;
            *(float4*)&s_x[c][j4 * 4] = *(const float4*)(xb + c * 16384 + i * 128 + j4 * 4);
        }
        __syncthreads();
        // fused: dots d[q] = <ncen_m, x[:,j0+q]>  and column norms n[q] = ||x[:,j0+q]||^2
        float d0 = 0.f, d1 = 0.f, d2 = 0.f, d3 = 0.f;
        float n0 = 0.f, n1 = 0.f, n2 = 0.f, n3 = 0.f;
        #pragma unroll
        for (int c4 = 0; c4 < 8; c4++) {
            float4 nc = *(const float4*)&s_ncen[m * 32 + c4 * 4];
            float4 xa = *(const float4*)&s_x[c4 * 4 + 0][j0];
            float4 xb_ = *(const float4*)&s_x[c4 * 4 + 1][j0];
            float4 xc = *(const float4*)&s_x[c4 * 4 + 2][j0];
            float4 xd = *(const float4*)&s_x[c4 * 4 + 3][j0];
            d0 += nc.x * xa.x + nc.y * xb_.x + nc.z * xc.x + nc.w * xd.x;
            d1 += nc.x * xa.y + nc.y * xb_.y + nc.z * xc.y + nc.w * xd.y;
            d2 += nc.x * xa.z + nc.y * xb_.z + nc.z * xc.z + nc.w * xd.z;
            d3 += nc.x * xa.w + nc.y * xb_.w + nc.z * xc.w + nc.w * xd.w;
            n0 += xa.x * xa.x + xb_.x * xb_.x + xc.x * xc.x + xd.x * xd.x;
            n1 += xa.y * xa.y + xb_.y * xb_.y + xc.y * xc.y + xd.y * xd.y;
            n2 += xa.z * xa.z + xb_.z * xb_.z + xc.z * xc.z + xd.z * xd.z;
            n3 += xa.w * xa.w + xb_.w * xb_.w + xc.w * xc.w + xd.w * xd.w;
        }
        float4 sg2 = *(const float4*)(sgb + i * 64 + j0);
        float i0 = 1.f / fmaxf(sqrtf(n0), 1e-12f);
        float i1 = 1.f / fmaxf(sqrtf(n1), 1e-12f);
        float i2 = 1.f / fmaxf(sqrtf(n2), 1e-12f);
        float i3 = 1.f / fmaxf(sqrtf(n3), 1e-12f);
        float s0 = sigmoidf(beta + alpha * d0 * i0) * sg2.x;
        float s1 = sigmoidf(beta + alpha * d1 * i1) * sg2.y;
        float s2 = sigmoidf(beta + alpha * d2 * i2) * sg2.z;
        float s3 = sigmoidf(beta + alpha * d3 * i3) * sg2.w;
        *(float4*)(simb + i * 64 + j0) = make_float4(s0, s1, s2, s3);
        __syncthreads();
    }
}

// ---------------- kernel B1: T = sim@x^T, S = rowsum(sim), G = sim@sim^T ----------------
// CTA per (bb, chunk): K-range 512 of 4096, 4 subtiles of 128.
__global__ __launch_bounds__(256) void k_T(const float* __restrict__ x) {
    __shared__ float s_x[32][132];
    __shared__ float s_sim[16][132];
    int blk = blockIdx.x;                  // 0..1023
    int bb = blk >> 3, chunk = blk & 7;
    int t = threadIdx.x;
    int m = t >> 4, c = t & 15;            // T roles; G roles: (ma=m, mb=c)
    int b = bb >> 5, e = (bb >> 2) & 7, f1 = (bb >> 1) & 1, f2 = bb & 1;
    const float* xb = x + (((size_t)(b * 256 + e * 32)) << 14) + (f1 * 64) * 128 + f2 * 64;
    const float* simb = d_sim + (size_t)bb * 65536;

    float T0 = 0.f, T1 = 0.f, Greg = 0.f, Sacc = 0.f;

    for (int sub = 0; sub < 4; sub++) {
        int i0 = chunk * 8 + sub * 2;
        int n0 = chunk * 512 + sub * 128;
        #pragma unroll
        for (int r = 0; r < 4; r++) {      // x: 32c x 128 (2 rows x 64)
            int v = r * 256 + t;
            int cc = v >> 5, kk = v & 31;
            int row = kk >> 4, j4 = kk & 15;
            *(float4*)&s_x[cc][kk * 4] =
                *(const float4*)(xb + cc * 16384 + (i0 + row) * 128 + j4 * 4);
        }
        #pragma unroll
        for (int r = 0; r < 2; r++) {      // sim: 16m x 128 (contiguous)
            int v = r * 256 + t;
            int mm = v >> 5, kk = v & 31;
            *(float4*)&s_sim[mm][kk * 4] = *(const float4*)(simb + mm * 4096 + n0 + kk * 4);
        }
        __syncthreads();
        #pragma unroll
        for (int k4 = 0; k4 < 32; k4++) {
            float4 a  = *(const float4*)&s_sim[m][k4 * 4];
            float4 bq = *(const float4*)&s_sim[c][k4 * 4];
            float4 xa = *(const float4*)&s_x[c][k4 * 4];
            float4 xc = *(const float4*)&s_x[c + 16][k4 * 4];
            T0 += a.x * xa.x + a.y * xa.y + a.z * xa.z + a.w * xa.w;
            T1 += a.x * xc.x + a.y * xc.y + a.z * xc.z + a.w * xc.w;
            Greg += a.x * bq.x + a.y * bq.y + a.z * bq.z + a.w * bq.w;
            if (c == 0) Sacc += (a.x + a.y) + (a.z + a.w);
        }
        __syncthreads();
    }
    d_Tp[blk * 512 + m * 32 + c]      = T0;
    d_Tp[blk * 512 + m * 32 + c + 16] = T1;
    d_Gp[blk * 256 + t] = Greg;            // t = ma*16 + mb, matches k_dout layout
    if (c == 0) d_Sp[blk * 16 + m] = Sacc;
}

// ---------- kernel B2: reduce partials -> dout, D, GN stat contributions ----------
__global__ __launch_bounds__(256) void k_dout() {
    __shared__ float s_S[16];
    __shared__ float s_dout[512];
    __shared__ double s_redd[16];
    int bb = blockIdx.x;
    int t = threadIdx.x;
    int b = bb >> 5;

    if (t < 16) {
        float s = 0.f;
        #pragma unroll
        for (int ch = 0; ch < 8; ch++) s += d_Sp[(bb * 8 + ch) * 16 + t];
        s_S[t] = s;
    }
    float Ta = 0.f, Tb = 0.f;
    #pragma unroll
    for (int ch = 0; ch < 8; ch++) {
        Ta += d_Tp[(bb * 8 + ch) * 512 + t];
        Tb += d_Tp[(bb * 8 + ch) * 512 + t + 256];
    }
    float Gf = 0.f;
    #pragma unroll
    for (int ch = 0; ch < 8; ch++) Gf += d_Gp[(bb * 8 + ch) * 256 + t];
    __syncthreads();

    int m1 = t >> 5, m2 = m1 + 8;
    float da = (Ta + d_cen[bb * 512 + t])       / (s_S[m1] + 1.f);
    float db = (Tb + d_cen[bb * 512 + t + 256]) / (s_S[m2] + 1.f);
    s_dout[t] = da; s_dout[t + 256] = db;
    d_dout[bb * 512 + t] = da;
    d_dout[bb * 512 + t + 256] = db;
    __syncthreads();

    int ma = t >> 4, mb = t & 15;
    float D = 0.f;
    #pragma unroll
    for (int c = 0; c < 32; c++) D += s_dout[ma * 32 + c] * s_dout[mb * 32 + c];

    double ds = (double)(da * s_S[m1] + db * s_S[m2]);  // sum(pre) contribution
    double d2 = (double)(Gf * D);                        // sumsq(pre) contribution
    #pragma unroll
    for (int o = 16; o; o >>= 1) {
        ds += __shfl_down_sync(0xffffffffu, ds, o);
        d2 += __shfl_down_sync(0xffffffffu, d2, o);
    }
    int wid = t >> 5, lane = t & 31;
    if (lane == 0) { s_redd[wid] = ds; s_redd[8 + wid] = d2; }
    __syncthreads();
    if (t == 0) {
        double a = 0.0, bq = 0.0;
        for (int w2 = 0; w2 < 8; w2++) { a += s_redd[w2]; bq += s_redd[8 + w2]; }
        atomicAdd(&d_gstats[b * 2], a);
        atomicAdd(&d_gstats[b * 2 + 1], bq);
    }
}

// ---------------- kernel D: fold GN scale into projection weights ----------------
__global__ void k_weff(const float* __restrict__ Wp, const float* __restrict__ gnw) {
    int idx = blockIdx.x * 256 + threadIdx.x;   // 262144
    int b = idx >> 16, oc = idx & 65535, c = idx & 255;
    double cnt = 4194304.0;
    double mu = d_gstats[b * 2] / cnt;
    double var = d_gstats[b * 2 + 1] / cnt - mu * mu;
    float inv = (float)(1.0 / sqrt(var + 1e-5));
    d_weff[idx] = Wp[oc] * inv * gnw[c];
}

// ---------------- kernel E: fold GN shift into projection bias ----------------
__global__ void k_beff(const float* __restrict__ Wp, const float* __restrict__ gnw,
                       const float* __restrict__ gnb, const float* __restrict__ bp) {
    int q = blockIdx.x * 8 + (threadIdx.x >> 5);   // 1024 warps
    int lane = threadIdx.x & 31;
    int b = q >> 8, o = q & 255;
    double cnt = 4194304.0;
    double mud = d_gstats[b * 2] / cnt;
    double var = d_gstats[b * 2 + 1] / cnt - mud * mud;
    float inv = (float)(1.0 / sqrt(var + 1e-5));
    float mu = (float)mud;
    float acc = 0.f;
    for (int c = lane; c < 256; c += 32) {
        float dc = gnb[c] - mu * inv * gnw[c];
        acc += dc * Wp[o * 256 + c];
    }
    #pragma unroll
    for (int off = 16; off; off >>= 1) acc += __shfl_down_sync(0xffffffffu, acc, off);
    if (lane == 0) d_beff[q] = bp[o] + acc;
}

// -------- kernel WD: WD[tile][o][e*16+m] = sum_c Weff[b][o][e*32+c]*dout[bb][m][c] --------
__global__ __launch_bounds__(256) void k_wd() {
    __shared__ float s_dout[512];
    int bb = blockIdx.x;
    int t = threadIdx.x;
    int b = bb >> 5, e = (bb >> 2) & 7;
    int tile = b * 4 + (bb & 3);            // (b, f1, f2)
    s_dout[t] = d_dout[bb * 512 + t];
    s_dout[t + 256] = d_dout[bb * 512 + t + 256];
    __syncthreads();
    const float* W = d_weff + b * 65536 + t * 256 + e * 32;   // row o=t
    float acc[16];
    #pragma unroll
    for (int m = 0; m < 16; m++) acc[m] = 0.f;
    #pragma unroll
    for (int c = 0; c < 32; c++) {
        float wv = W[c];
        #pragma unroll
        for (int m = 0; m < 16; m++) acc[m] += wv * s_dout[m * 32 + c];
    }
    float* dst = d_WD + tile * 32768 + t * 128 + e * 16;
    #pragma unroll
    for (int m = 0; m < 16; m++) dst[m] = acc[m];
}

// -------- kernel F: out[o][n] = silu(beff[o] + sum_q WD[o][q]*sim[q][n]) --------
// 128o x 128n per CTA, 8x8 register tile per thread, K=128 in chunks of 16.
__global__ __launch_bounds__(256) void k_out(float* __restrict__ out) {
    __shared__ float Ws[16][132];
    __shared__ float Ps[16][132];
    int nb = blockIdx.x * 128;              // 32 blocks
    int ob = blockIdx.y * 128;              // 2 blocks
    int tile = blockIdx.z;                  // 16
    int b = tile >> 2, f1 = (tile >> 1) & 1, f2 = tile & 1;
    int t = threadIdx.x;
    int tx = t & 15, ty = t >> 4;
    const float* W = d_WD + tile * 32768;

    float acc[8][8];
    #pragma unroll
    for (int a = 0; a < 8; a++)
        #pragma unroll
        for (int q = 0; q < 8; q++) acc[a][q] = 0.f;

    for (int k0 = 0; k0 < 128; k0 += 16) {
        #pragma unroll
        for (int r = 0; r < 2; r++) {       // W: 128o x 16k, transpose to Ws[k][o]
            int v = r * 256 + t;
            int o = v >> 2, k4 = v & 3;
            float4 w4 = *(const float4*)(W + (ob + o) * 128 + k0 + k4 * 4);
            Ws[k4 * 4 + 0][o] = w4.x; Ws[k4 * 4 + 1][o] = w4.y;
            Ws[k4 * 4 + 2][o] = w4.z; Ws[k4 * 4 + 3][o] = w4.w;
        }
        #pragma unroll
        for (int r = 0; r < 2; r++) {       // P: 16k x 128n, direct copy
            int v = r * 256 + t;
            int k = v >> 5, n4 = v & 31;
            int q = k0 + k;                 // q = e*16 + m
            int bbq = b * 32 + (q >> 4) * 4 + f1 * 2 + f2;
            const float* srow = d_sim + (size_t)bbq * 65536 + (q & 15) * 4096 + nb;
            *(float4*)&Ps[k][n4 * 4] = *(const float4*)(srow + n4 * 4);
        }
        __syncthreads();
        #pragma unroll
        for (int k = 0; k < 16; k++) {
            float wr[8], pr[8];
            *(float4*)wr       = *(const float4*)&Ws[k][ty * 8];
            *(float4*)(wr + 4) = *(const float4*)&Ws[k][ty * 8 + 4];
            *(float4*)pr       = *(const float4*)&Ps[k][tx * 8];
            *(float4*)(pr + 4) = *(const float4*)&Ps[k][tx * 8 + 4];
            #pragma unroll
            for (int a = 0; a < 8; a++)
                #pragma unroll
                for (int q = 0; q < 8; q++) acc[a][q] += wr[a] * pr[q];
        }
        __syncthreads();
    }
    int nloc = nb + tx * 8;                 // local n within 64x64 tile
    int irow = nloc >> 6, jcol = nloc & 63;
    #pragma unroll
    for (int a = 0; a < 8; a++) {
        int o = ob + ty * 8 + a;
        float bias = d_beff[b * 256 + o];
        float r[8];
        #pragma unroll
        for (int q = 0; q < 8; q++) {
            float z = acc[a][q] + bias;
            r[q] = z * sigmoidf(z);
        }
        float* orow = out + (((size_t)(b * 256 + o)) << 14)
                          + (f1 * 64 + irow) * 128 + f2 * 64 + jcol;
        *(float4*)orow       = make_float4(r[0], r[1], r[2], r[3]);
        *(float4*)(orow + 4) = make_float4(r[4], r[5], r[6], r[7]);
    }
}

// ---------------- launch ----------------
extern "C" void kernel_launch(void* const* d_in, const int* in_sizes, int n_in,
                              void* d_out, int out_size) {
    const float* x     = (const float*)d_in[0];
    const float* xyz   = (const float*)d_in[1];
    // d_in[2]=Wv, d_in[3]=bv : dead code (split path multiplied by zero mask)
    const float* Wproj = (const float*)d_in[4];
    const float* bproj = (const float*)d_in[5];
    const float* gnw   = (const float*)d_in[6];
    const float* gnb   = (const float*)d_in[7];
    const float* sa    = (const float*)d_in[8];
    const float* sb    = (const float*)d_in[9];
    float* out = (float*)d_out;

    k_centers<<<8192, 256>>>(x);
    k_ncen<<<256, 256>>>();
    k_geo<<<1, 256>>>(xyz);
    k_geo2<<<dim3(16, 64), 256>>>(xyz, sa, sb);
    k_sim<<<1024, 256>>>(x, sa, sb);
    k_T<<<1024, 256>>>(x);
    k_dout<<<128, 256>>>();
    k_weff<<<1024, 256>>>(Wproj, gnw);
    k_beff<<<128, 256>>>(Wproj, gnw, gnb, bproj);
    k_wd<<<128, 256>>>();
    k_out<<<dim3(32, 2, 16), 256>>>(out);
}

// round 8
// speedup vs baseline: 2.2255x; 1.1286x over previous
#include <cuda_runtime.h>
#include <math.h>

// x: (4,256,128,128)  xyz: (4,3,128,128)
// folded blocks: NB=128 (b*32 + e*4 + f1*2 + f2), c=32, tile 64x64, M=16 centers
#define NB 128
#define MCNT 16

// ---------------- scratch (static __device__, no allocation) ----------------
__device__ float  d_cen [NB*512];         // pooled centers (unnormalized)
__device__ float  d_ncen[NB*512];         // l2-normalized centers
__device__ float  d_ngeo[16*16*4];        // normalized xyz centers, padded to 4
__device__ float  d_sgeo2[16*16*4096];    // sigmoid(geo)^2 table  [g][m][n]  (4 MB)
__device__ float  d_sim [NB*16*4096];     // 33.5 MB sim cache (tf32-rounded values)
__device__ float  d_Tp  [1024*512];       // partial T = sim@x  (per bb-chunk)
__device__ float  d_Sp  [1024*16];        // partial rowsum(sim)
__device__ float  d_Gp  [1024*256];       // partial Gram(sim)
__device__ float  d_dout[NB*512];         // dense_out (16m x 32c per bb)
__device__ double d_gstats[8];            // per-batch sum, sumsq
__device__ float  d_weff[4*256*256];      // GN-folded projection weights
__device__ float  d_beff[4*256];          // GN-folded projection bias
__device__ float  d_WD  [16*256*128];     // fused weights (tf32-rounded)

__device__ __forceinline__ float sigmoidf(float z) { return 1.f / (1.f + __expf(-z)); }
__device__ __forceinline__ float f2tf(float f) {
    unsigned u; asm("cvt.rna.tf32.f32 %0, %1;" : "=r"(u) : "f"(f));
    return __uint_as_float(u);
}

// ---------------- kernel A: pooled centers, warp per (bb,m,c), float4 ----------------
__global__ void k_centers(const float* __restrict__ x) {
    int w = blockIdx.x * 8 + (threadIdx.x >> 5);   // 65536 warps
    int lane = threadIdx.x & 31;
    int bb = w >> 9; int rem = w & 511; int m = rem >> 5; int c = rem & 31;
    int b = bb >> 5, e = (bb >> 2) & 7, f1 = (bb >> 1) & 1, f2 = bb & 1;
    int pi = m >> 2, pj = m & 3;
    const float* xp = x + (((size_t)(b * 256 + e * 32 + c)) << 14)
                        + (f1 * 64 + pi * 16) * 128 + f2 * 64 + pj * 16;
    float acc = 0.f;
    #pragma unroll
    for (int r = 0; r < 2; r++) {
        int idx = r * 32 + lane;              // 0..63 float4s
        int ii = idx >> 2, jj4 = idx & 3;
        float4 v = *(const float4*)(xp + ii * 128 + jj4 * 4);
        acc += (v.x + v.y) + (v.z + v.w);
    }
    #pragma unroll
    for (int o = 16; o; o >>= 1) acc += __shfl_down_sync(0xffffffffu, acc, o);
    if (lane == 0) d_cen[w] = acc * (1.f / 256.f);
}

// ---------------- kernel A2: normalize centers, warp per (bb,m) ----------------
__global__ void k_ncen() {
    int q = blockIdx.x * 8 + (threadIdx.x >> 5);   // 2048 warps
    int c = threadIdx.x & 31;
    float v = d_cen[q * 32 + c];
    float ss = v * v;
    #pragma unroll
    for (int o = 16; o; o >>= 1) ss += __shfl_xor_sync(0xffffffffu, ss, o);
    float inv = 1.f / fmaxf(sqrtf(ss), 1e-12f);
    d_ncen[q * 32 + c] = v * inv;
}

// ---------------- kernel A3: normalized xyz centers + zero stats ----------------
__global__ void k_geo(const float* __restrict__ xyz) {
    int t = threadIdx.x;
    if (t < 8) d_gstats[t] = 0.0;
    int g = t >> 4, m = t & 15;
    int b = g >> 2, f1 = (g >> 1) & 1, f2 = g & 1;
    int pi = m >> 2, pj = m & 3;
    const float* base = xyz + (((size_t)(b * 3)) << 14)
                            + (f1 * 64 + pi * 16) * 128 + f2 * 64 + pj * 16;
    float s0 = 0.f, s1 = 0.f, s2 = 0.f;
    for (int ii = 0; ii < 16; ii++)
        for (int jj = 0; jj < 16; jj++) {
            int off = ii * 128 + jj;
            s0 += base[off];
            s1 += base[off + 16384];
            s2 += base[off + 32768];
        }
    s0 *= (1.f / 256.f); s1 *= (1.f / 256.f); s2 *= (1.f / 256.f);
    float inv = 1.f / fmaxf(sqrtf(s0 * s0 + s1 * s1 + s2 * s2), 1e-12f);
    int o = (g * 16 + m) * 4;
    d_ngeo[o] = s0 * inv; d_ngeo[o + 1] = s1 * inv; d_ngeo[o + 2] = s2 * inv; d_ngeo[o + 3] = 0.f;
}

// ---------------- kernel A4: sim_geo^2 table [g][m][n], grid (16 g, 64 i) ----------------
__global__ void k_geo2(const float* __restrict__ xyz,
                       const float* __restrict__ salpha, const float* __restrict__ sbeta) {
    int g = blockIdx.x, i = blockIdx.y;
    int t = threadIdx.x;
    int j = t & 63, mg = t >> 6;                 // 4 m-groups of 4
    int bg = g >> 2, f1 = (g >> 1) & 1, f2 = g & 1;
    float alpha = salpha[0], beta = sbeta[0];
    const float* base = xyz + (((size_t)(bg * 3)) << 14) + (f1 * 64 + i) * 128 + f2 * 64 + j;
    float p0 = base[0], p1 = base[16384], p2 = base[32768];
    float inv = 1.f / fmaxf(sqrtf(p0 * p0 + p1 * p1 + p2 * p2), 1e-12f);
    p0 *= inv; p1 *= inv; p2 *= inv;
    #pragma unroll
    for (int mm = 0; mm < 4; mm++) {
        int m = mg * 4 + mm;
        const float* ng = d_ngeo + (g * 16 + m) * 4;
        float gd = ng[0] * p0 + ng[1] * p1 + ng[2] * p2;
        float sg = sigmoidf(beta + alpha * gd);
        d_sgeo2[(g * 16 + m) * 4096 + i * 64 + j] = sg * sg;
    }
}

// ---------------- kernel B: sim pass (lean), CTA per (bb, 8-row chunk) ----------------
// thread = (m = t>>4, jq = t&15): computes sim[m][j0..j0+3], stores tf32-rounded.
__global__ __launch_bounds__(256) void k_sim(const float* __restrict__ x,
                                             const float* __restrict__ salpha,
                                             const float* __restrict__ sbeta) {
    __shared__ float s_ncen[512];
    __shared__ float s_x[32][68];

    int blk = blockIdx.x;                  // 0..1023
    int bb = blk >> 3, chunk = blk & 7;
    int t = threadIdx.x;
    int m = t >> 4, jq = t & 15, j0 = jq * 4;
    int b = bb >> 5, e = (bb >> 2) & 7, f1 = (bb >> 1) & 1, f2 = bb & 1;
    int g = bb & 15;        // reference's tile() quirk: geo block = bb % 16
    float alpha = salpha[0], beta = sbeta[0];

    s_ncen[t]       = d_ncen[bb * 512 + t];
    s_ncen[t + 256] = d_ncen[bb * 512 + t + 256];

    const float* xb = x + (((size_t)(b * 256 + e * 32)) << 14) + (f1 * 64) * 128 + f2 * 64;
    float* simb = d_sim + (size_t)bb * 65536 + m * 4096;
    const float* sgb = d_sgeo2 + (g * 16 + m) * 4096;
    __syncthreads();

    for (int ir = 0; ir < 8; ir++) {
        int i = chunk * 8 + ir;
        #pragma unroll
        for (int r = 0; r < 2; r++) {
            int v = r * 256 + t;
            int c = v >> 4, j4 = v & 15;
            *(float4*)&s_x[c][j4 * 4] = *(const float4*)(xb + c * 16384 + i * 128 + j4 * 4);
        }
        __syncthreads();
        float d0 = 0.f, d1 = 0.f, d2 = 0.f, d3 = 0.f;
        float n0 = 0.f, n1 = 0.f, n2 = 0.f, n3 = 0.f;
        #pragma unroll
        for (int c4 = 0; c4 < 8; c4++) {
            float4 nc = *(const float4*)&s_ncen[m * 32 + c4 * 4];
            float4 xa = *(const float4*)&s_x[c4 * 4 + 0][j0];
            float4 xb_ = *(const float4*)&s_x[c4 * 4 + 1][j0];
            float4 xc = *(const float4*)&s_x[c4 * 4 + 2][j0];
            float4 xd = *(const float4*)&s_x[c4 * 4 + 3][j0];
            d0 += nc.x * xa.x + nc.y * xb_.x + nc.z * xc.x + nc.w * xd.x;
            d1 += nc.x * xa.y + nc.y * xb_.y + nc.z * xc.y + nc.w * xd.y;
            d2 += nc.x * xa.z + nc.y * xb_.z + nc.z * xc.z + nc.w * xd.z;
            d3 += nc.x * xa.w + nc.y * xb_.w + nc.z * xc.w + nc.w * xd.w;
            n0 += xa.x * xa.x + xb_.x * xb_.x + xc.x * xc.x + xd.x * xd.x;
            n1 += xa.y * xa.y + xb_.y * xb_.y + xc.y * xc.y + xd.y * xd.y;
            n2 += xa.z * xa.z + xb_.z * xb_.z + xc.z * xc.z + xd.z * xd.z;
            n3 += xa.w * xa.w + xb_.w * xb_.w + xc.w * xc.w + xd.w * xd.w;
        }
        float4 sg2 = *(const float4*)(sgb + i * 64 + j0);
        float i0 = 1.f / fmaxf(sqrtf(n0), 1e-12f);
        float i1 = 1.f / fmaxf(sqrtf(n1), 1e-12f);
        float i2 = 1.f / fmaxf(sqrtf(n2), 1e-12f);
        float i3 = 1.f / fmaxf(sqrtf(n3), 1e-12f);
        float s0 = f2tf(sigmoidf(beta + alpha * d0 * i0) * sg2.x);
        float s1 = f2tf(sigmoidf(beta + alpha * d1 * i1) * sg2.y);
        float s2 = f2tf(sigmoidf(beta + alpha * d2 * i2) * sg2.z);
        float s3 = f2tf(sigmoidf(beta + alpha * d3 * i3) * sg2.w);
        *(float4*)(simb + i * 64 + j0) = make_float4(s0, s1, s2, s3);
        __syncthreads();
    }
}

// ---------------- kernel B1: T = sim@x^T, S = rowsum(sim), G = sim@sim^T ----------------
__global__ __launch_bounds__(256) void k_T(const float* __restrict__ x) {
    __shared__ float s_x[32][132];
    __shared__ float s_sim[16][132];
    int blk = blockIdx.x;                  // 0..1023
    int bb = blk >> 3, chunk = blk & 7;
    int t = threadIdx.x;
    int m = t >> 4, c = t & 15;            // T roles; G roles: (ma=m, mb=c)
    int b = bb >> 5, e = (bb >> 2) & 7, f1 = (bb >> 1) & 1, f2 = bb & 1;
    const float* xb = x + (((size_t)(b * 256 + e * 32)) << 14) + (f1 * 64) * 128 + f2 * 64;
    const float* simb = d_sim + (size_t)bb * 65536;

    float T0 = 0.f, T1 = 0.f, Greg = 0.f, Sacc = 0.f;

    for (int sub = 0; sub < 4; sub++) {
        int i0 = chunk * 8 + sub * 2;
        int n0 = chunk * 512 + sub * 128;
        #pragma unroll
        for (int r = 0; r < 4; r++) {      // x: 32c x 128 (2 rows x 64)
            int v = r * 256 + t;
            int cc = v >> 5, kk = v & 31;
            int row = kk >> 4, j4 = kk & 15;
            *(float4*)&s_x[cc][kk * 4] =
                *(const float4*)(xb + cc * 16384 + (i0 + row) * 128 + j4 * 4);
        }
        #pragma unroll
        for (int r = 0; r < 2; r++) {      // sim: 16m x 128 (contiguous)
            int v = r * 256 + t;
            int mm = v >> 5, kk = v & 31;
            *(float4*)&s_sim[mm][kk * 4] = *(const float4*)(simb + mm * 4096 + n0 + kk * 4);
        }
        __syncthreads();
        #pragma unroll
        for (int k4 = 0; k4 < 32; k4++) {
            float4 a  = *(const float4*)&s_sim[m][k4 * 4];
            float4 bq = *(const float4*)&s_sim[c][k4 * 4];
            float4 xa = *(const float4*)&s_x[c][k4 * 4];
            float4 xc = *(const float4*)&s_x[c + 16][k4 * 4];
            T0 += a.x * xa.x + a.y * xa.y + a.z * xa.z + a.w * xa.w;
            T1 += a.x * xc.x + a.y * xc.y + a.z * xc.z + a.w * xc.w;
            Greg += a.x * bq.x + a.y * bq.y + a.z * bq.z + a.w * bq.w;
            if (c == 0) Sacc += (a.x + a.y) + (a.z + a.w);
        }
        __syncthreads();
    }
    d_Tp[blk * 512 + m * 32 + c]      = T0;
    d_Tp[blk * 512 + m * 32 + c + 16] = T1;
    d_Gp[blk * 256 + t] = Greg;            // t = ma*16 + mb
    if (c == 0) d_Sp[blk * 16 + m] = Sacc;
}

// ---------- kernel B2: reduce partials -> dout, D, GN stat contributions ----------
__global__ __launch_bounds__(256) void k_dout() {
    __shared__ float s_S[16];
    __shared__ float s_dout[512];
    __shared__ double s_redd[16];
    int bb = blockIdx.x;
    int t = threadIdx.x;
    int b = bb >> 5;

    if (t < 16) {
        float s = 0.f;
        #pragma unroll
        for (int ch = 0; ch < 8; ch++) s += d_Sp[(bb * 8 + ch) * 16 + t];
        s_S[t] = s;
    }
    float Ta = 0.f, Tb = 0.f;
    #pragma unroll
    for (int ch = 0; ch < 8; ch++) {
        Ta += d_Tp[(bb * 8 + ch) * 512 + t];
        Tb += d_Tp[(bb * 8 + ch) * 512 + t + 256];
    }
    float Gf = 0.f;
    #pragma unroll
    for (int ch = 0; ch < 8; ch++) Gf += d_Gp[(bb * 8 + ch) * 256 + t];
    __syncthreads();

    int m1 = t >> 5, m2 = m1 + 8;
    float da = (Ta + d_cen[bb * 512 + t])       / (s_S[m1] + 1.f);
    float db = (Tb + d_cen[bb * 512 + t + 256]) / (s_S[m2] + 1.f);
    s_dout[t] = da; s_dout[t + 256] = db;
    d_dout[bb * 512 + t] = da;
    d_dout[bb * 512 + t + 256] = db;
    __syncthreads();

    int ma = t >> 4, mb = t & 15;
    float D = 0.f;
    #pragma unroll
    for (int c = 0; c < 32; c++) D += s_dout[ma * 32 + c] * s_dout[mb * 32 + c];

    double ds = (double)(da * s_S[m1] + db * s_S[m2]);  // sum(pre) contribution
    double d2 = (double)(Gf * D);                        // sumsq(pre) contribution
    #pragma unroll
    for (int o = 16; o; o >>= 1) {
        ds += __shfl_down_sync(0xffffffffu, ds, o);
        d2 += __shfl_down_sync(0xffffffffu, d2, o);
    }
    int wid = t >> 5, lane = t & 31;
    if (lane == 0) { s_redd[wid] = ds; s_redd[8 + wid] = d2; }
    __syncthreads();
    if (t == 0) {
        double a = 0.0, bq = 0.0;
        for (int w2 = 0; w2 < 8; w2++) { a += s_redd[w2]; bq += s_redd[8 + w2]; }
        atomicAdd(&d_gstats[b * 2], a);
        atomicAdd(&d_gstats[b * 2 + 1], bq);
    }
}

// ---------------- kernel D: fold GN scale into projection weights ----------------
__global__ void k_weff(const float* __restrict__ Wp, const float* __restrict__ gnw) {
    int idx = blockIdx.x * 256 + threadIdx.x;   // 262144
    int b = idx >> 16, oc = idx & 65535, c = idx & 255;
    double cnt = 4194304.0;
    double mu = d_gstats[b * 2] / cnt;
    double var = d_gstats[b * 2 + 1] / cnt - mu * mu;
    float inv = (float)(1.0 / sqrt(var + 1e-5));
    d_weff[idx] = Wp[oc] * inv * gnw[c];
}

// ---------------- kernel E: fold GN shift into projection bias ----------------
__global__ void k_beff(const float* __restrict__ Wp, const float* __restrict__ gnw,
                       const float* __restrict__ gnb, const float* __restrict__ bp) {
    int q = blockIdx.x * 8 + (threadIdx.x >> 5);   // 1024 warps
    int lane = threadIdx.x & 31;
    int b = q >> 8, o = q & 255;
    double cnt = 4194304.0;
    double mud = d_gstats[b * 2] / cnt;
    double var = d_gstats[b * 2 + 1] / cnt - mud * mud;
    float inv = (float)(1.0 / sqrt(var + 1e-5));
    float mu = (float)mud;
    float acc = 0.f;
    for (int c = lane; c < 256; c += 32) {
        float dc = gnb[c] - mu * inv * gnw[c];
        acc += dc * Wp[o * 256 + c];
    }
    #pragma unroll
    for (int off = 16; off; off >>= 1) acc += __shfl_down_sync(0xffffffffu, acc, off);
    if (lane == 0) d_beff[q] = bp[o] + acc;
}

// -------- kernel WD: WD[tile][o][e*16+m] = sum_c Weff[b][o][e*32+c]*dout[bb][m][c] --------
__global__ __launch_bounds__(256) void k_wd() {
    __shared__ float s_dout[512];
    int bb = blockIdx.x;
    int t = threadIdx.x;
    int b = bb >> 5, e = (bb >> 2) & 7;
    int tile = b * 4 + (bb & 3);            // (b, f1, f2)
    s_dout[t] = d_dout[bb * 512 + t];
    s_dout[t + 256] = d_dout[bb * 512 + t + 256];
    __syncthreads();
    const float* W = d_weff + b * 65536 + t * 256 + e * 32;   // row o=t
    float acc[16];
    #pragma unroll
    for (int m = 0; m < 16; m++) acc[m] = 0.f;
    #pragma unroll
    for (int c = 0; c < 32; c++) {
        float wv = W[c];
        #pragma unroll
        for (int m = 0; m < 16; m++) acc[m] += wv * s_dout[m * 32 + c];
    }
    float* dst = d_WD + tile * 32768 + t * 128 + e * 16;
    #pragma unroll
    for (int m = 0; m < 16; m++) dst[m] = f2tf(acc[m]);
}

// -------- kernel F: out[o][n] = silu(beff[o] + WD @ sim), tf32 tensor cores --------
// CTA 128o x 128n, 8 warps of 64o x 32n, K=128 in chunks of 32, mma.m16n8k4.
__global__ __launch_bounds__(256) void k_out(float* __restrict__ out) {
    __shared__ float SB[8960];              // Ws[128][36] | Ps[32][136]; epilogue Sout[64][132]
    float* Ws = SB;
    float* Ps = SB + 4608;
    int nb = blockIdx.x * 128;              // 32
    int ob = blockIdx.y * 128;              // 2
    int tile = blockIdx.z;                  // 16
    int b = tile >> 2, f1 = (tile >> 1) & 1, f2 = tile & 1;
    int t = threadIdx.x;
    int w = t >> 5, lane = t & 31;
    int g = lane >> 2, tid = lane & 3;
    int wo = w >> 2, wn = w & 3;            // warp: o = wo*64.., n = wn*32..
    const float* W = d_WD + tile * 32768;

    float acc[4][4][4];
    #pragma unroll
    for (int mt = 0; mt < 4; mt++)
        #pragma unroll
        for (int nt = 0; nt < 4; nt++)
            #pragma unroll
            for (int r = 0; r < 4; r++) acc[mt][nt][r] = 0.f;

    for (int k0 = 0; k0 < 128; k0 += 32) {
        #pragma unroll
        for (int r = 0; r < 4; r++) {       // Ws: 128o x 32k (already tf32-rounded)
            int idx = r * 256 + t;
            int o = idx >> 3, k4 = idx & 7;
            *(float4*)&Ws[o * 36 + k4 * 4] =
                *(const float4*)(W + (ob + o) * 128 + k0 + k4 * 4);
        }
        #pragma unroll
        for (int r = 0; r < 4; r++) {       // Ps: 32k x 128n
            int idx = r * 256 + t;
            int k = idx >> 5, n4 = idx & 31;
            int q = k0 + k;                 // q = e*16 + m
            int bbq = b * 32 + (q >> 4) * 4 + f1 * 2 + f2;
            const float* srow = d_sim + (size_t)bbq * 65536 + (q & 15) * 4096 + nb;
            *(float4*)&Ps[k * 136 + n4 * 4] = *(const float4*)(srow + n4 * 4);
        }
        __syncthreads();
        #pragma unroll
        for (int kt = 0; kt < 8; kt++) {
            unsigned a0[4], a1[4], bf[4];
            #pragma unroll
            for (int mt = 0; mt < 4; mt++) {
                int row = wo * 64 + mt * 16;
                a0[mt] = __float_as_uint(Ws[(row + g) * 36 + kt * 4 + tid]);
                a1[mt] = __float_as_uint(Ws[(row + g + 8) * 36 + kt * 4 + tid]);
            }
            #pragma unroll
            for (int nt = 0; nt < 4; nt++)
                bf[nt] = __float_as_uint(Ps[(kt * 4 + tid) * 136 + wn * 32 + nt * 8 + g]);
            #pragma unroll
            for (int mt = 0; mt < 4; mt++)
                #pragma unroll
                for (int nt = 0; nt < 4; nt++)
                    asm volatile(
                        "mma.sync.aligned.m16n8k4.row.col.f32.tf32.tf32.f32 "
                        "{%0,%1,%2,%3}, {%4,%5}, {%6}, {%0,%1,%2,%3};"
                        : "+f"(acc[mt][nt][0]), "+f"(acc[mt][nt][1]),
                          "+f"(acc[mt][nt][2]), "+f"(acc[mt][nt][3])
                        : "r"(a0[mt]), "r"(a1[mt]), "r"(bf[nt]));
        }
        __syncthreads();
    }

    // epilogue: two o-halves via smem for coalesced float4 stores
    float* Sout = SB;                       // [64][132]
    #pragma unroll
    for (int h = 0; h < 2; h++) {
        if (wo == h) {
            #pragma unroll
            for (int mt = 0; mt < 4; mt++) {
                int r0 = mt * 16 + g;
                #pragma unroll
                for (int nt = 0; nt < 4; nt++) {
                    int col = wn * 32 + nt * 8 + 2 * tid;
                    Sout[r0 * 132 + col]           = acc[mt][nt][0];
                    Sout[r0 * 132 + col + 1]       = acc[mt][nt][1];
                    Sout[(r0 + 8) * 132 + col]     = acc[mt][nt][2];
                    Sout[(r0 + 8) * 132 + col + 1] = acc[mt][nt][3];
                }
            }
        }
        __syncthreads();
        #pragma unroll
        for (int r = 0; r < 8; r++) {
            int idx = r * 256 + t;          // 2048 float4
            int row = idx >> 5, n4 = idx & 31;
            int o = ob + h * 64 + row;
            float bias = d_beff[b * 256 + o];
            float4 v = *(const float4*)&Sout[row * 132 + n4 * 4];
            float z0 = v.x + bias, z1 = v.y + bias, z2 = v.z + bias, z3 = v.w + bias;
            float4 rr = make_float4(z0 * sigmoidf(z0), z1 * sigmoidf(z1),
                                    z2 * sigmoidf(z2), z3 * sigmoidf(z3));
            int nloc = nb + n4 * 4;
            int irow = nloc >> 6, jcol = nloc & 63;
            float* orow = out + (((size_t)(b * 256 + o)) << 14)
                              + (f1 * 64 + irow) * 128 + f2 * 64 + jcol;
            *(float4*)orow = rr;
        }
        __syncthreads();
    }
}

// ---------------- launch ----------------
extern "C" void kernel_launch(void* const* d_in, const int* in_sizes, int n_in,
                              void* d_out, int out_size) {
    const float* x     = (const float*)d_in[0];
    const float* xyz   = (const float*)d_in[1];
    // d_in[2]=Wv, d_in[3]=bv : dead code (split path multiplied by zero mask)
    const float* Wproj = (const float*)d_in[4];
    const float* bproj = (const float*)d_in[5];
    const float* gnw   = (const float*)d_in[6];
    const float* gnb   = (const float*)d_in[7];
    const float* sa    = (const float*)d_in[8];
    const float* sb    = (const float*)d_in[9];
    float* out = (float*)d_out;

    k_centers<<<8192, 256>>>(x);
    k_ncen<<<256, 256>>>();
    k_geo<<<1, 256>>>(xyz);
    k_geo2<<<dim3(16, 64), 256>>>(xyz, sa, sb);
    k_sim<<<1024, 256>>>(x, sa, sb);
    k_T<<<1024, 256>>>(x);
    k_dout<<<128, 256>>>();
    k_weff<<<1024, 256>>>(Wproj, gnw);
    k_beff<<<128, 256>>>(Wproj, gnw, gnb, bproj);
    k_wd<<<128, 256>>>();
    k_out<<<dim3(32, 2, 16), 256>>>(out);
}